// round 9
// baseline (speedup 1.0000x reference)
#include <cuda_runtime.h>
#include <cstdint>

// Problem constants
#define BB    8192
#define TT    100
#define TGTN  60

#define NT    256     // threads per CTA (8 warps)
#define BR    32      // batch rows per CTA
#define HPAD  36      // h row stride (floats)
#define CPAD  32      // c row stride (floats)
#define XPAD  32      // x/feedback row stride (floats)
#define CHUNKF 4096   // one weight buffer: [512 rows][8 k] floats (16KB)

// Shared layout (float offsets, all 16B-aligned)
#define OFF_H0   0                 // [128][36]
#define OFF_H1   4608              // [128][36]
#define OFF_C0   9216              // [128][32]
#define OFF_C1   13312             // [128][32]
#define OFF_WBUF 17408             // 2 x [512][8]
#define OFF_XS   25600             // [16][32]
#define OFF_FC   26112             // fcW [2][128]
#define OFF_FCB  26368             // fcb [2] + pad
#define OFF_DW   26372             // dWih0 native [512][2]
#define SMEM_FLOATS 27396
#define SMEM_BYTES  (SMEM_FLOATS*4)   // 109,584 B -> 2 CTAs/SM

typedef unsigned long long u64;

// ---- packed f32x2 helpers ----
__device__ __forceinline__ u64 pk2(float x) {
    u64 r; asm("mov.b64 %0, {%1, %1};" : "=l"(r) : "f"(x)); return r;
}
__device__ __forceinline__ u64 f2fma(u64 a, u64 b, u64 c) {
    u64 d; asm("fma.rn.f32x2 %0, %1, %2, %3;" : "=l"(d) : "l"(a), "l"(b), "l"(c)); return d;
}
__device__ __forceinline__ float2 up2(u64 v) {
    float2 f; asm("mov.b64 {%0, %1}, %2;" : "=f"(f.x), "=f"(f.y) : "l"(v)); return f;
}

// ---- activations ----
__device__ __forceinline__ float sigm(float x) {
    return __fdividef(1.0f, 1.0f + __expf(-x));
}
__device__ __forceinline__ float tanh_(float x) {
    float a = fabsf(x);
    float e = __expf(-2.0f * a);
    float t = __fdividef(1.0f - e, 1.0f + e);
    return copysignf(t, x);
}

__device__ __forceinline__ void init_acc(u64 acc[4][8], const float b[4])
{
#pragma unroll
    for (int g = 0; g < 4; g++) {
        u64 bb = pk2(b[g]);
#pragma unroll
        for (int p = 0; p < 8; p++) acc[g][p] = bb;
    }
}

// ---- streamed GEMM over K = NCH*8.
//      Weights: W [512][ldw] row-major global -> cp.async(8B) into [512][8]
//      buffers with XOR swizzle: word(r,k) = r*8 + (k ^ (2*((r>>2)&3))).
//      Activations: hb (= base + rb*16 floats), stride STRIDE per k.
//      Double buffer, one barrier per chunk, depth-1 prefetch. ----
template<int NCH, int STRIDE>
__device__ __forceinline__ void gemm_cp(u64 acc[4][8],
                                        const float* __restrict__ W, int ldw,
                                        const float* __restrict__ hb,
                                        const float* __restrict__ sm,
                                        uint32_t smem_u32, int tid, int j)
{
    const int r0 = tid * 2;
    const int kx = ((j >> 2) & 3) << 1;   // k-xor for this thread's gate rows

    auto issue = [&](int c) {
        int buf = c & 1;
#pragma unroll
        for (int rr = 0; rr < 2; rr++) {
            int r = r0 + rr;
            int s = (r >> 2) & 3;
            uint32_t dbase = smem_u32 + (uint32_t)((OFF_WBUF + buf * CHUNKF + r * 8) * 4);
            const float* src = W + (size_t)r * ldw + c * 8;
#pragma unroll
            for (int q = 0; q < 4; q++) {
                uint32_t dst = dbase + (uint32_t)(((q ^ s) << 3));
                asm volatile("cp.async.ca.shared.global [%0], [%1], 8;"
                             :: "r"(dst), "l"(src + q * 2));
            }
        }
        asm volatile("cp.async.commit_group;" ::: "memory");
    };

    issue(0);
#pragma unroll 1
    for (int c = 0; c < NCH; c++) {
        asm volatile("cp.async.wait_group 0;" ::: "memory");
        __syncthreads();                 // chunk c visible; other buffer's readers done
        if (c + 1 < NCH) issue(c + 1);
        const float* wb = sm + OFF_WBUF + (c & 1) * CHUNKF;
        const float* hc = hb + c * 8 * STRIDE;
#pragma unroll
        for (int k = 0; k < 8; k++) {
            int kk = k ^ kx;
            u64 b0 = pk2(wb[(j      ) * 8 + kk]);
            u64 b1 = pk2(wb[(j + 128) * 8 + kk]);
            u64 b2 = pk2(wb[(j + 256) * 8 + kk]);
            u64 b3 = pk2(wb[(j + 384) * 8 + kk]);
            const ulonglong2* hp = (const ulonglong2*)(hc + k * STRIDE);
            ulonglong2 q0 = hp[0], q1 = hp[1], q2 = hp[2], q3 = hp[3];
            u64 a[8] = {q0.x, q0.y, q1.x, q1.y, q2.x, q2.y, q3.x, q3.y};
#pragma unroll
            for (int p = 0; p < 8; p++) {
                acc[0][p] = f2fma(a[p], b0, acc[0][p]);
                acc[1][p] = f2fma(a[p], b1, acc[1][p]);
                acc[2][p] = f2fma(a[p], b2, acc[2][p]);
                acc[3][p] = f2fma(a[p], b3, acc[3][p]);
            }
        }
    }
    __syncthreads();   // protect h/x rewrites after this gemm from stragglers
}

// ---- LSTM pointwise epilogue: unit j, rows rb*16..rb*16+15; c in smem ----
__device__ __forceinline__ void epilogue(u64 acc[4][8],
                                         float* __restrict__ cs,
                                         float* __restrict__ hs,
                                         int j, int rb)
{
    float2* cp = (float2*)(cs + j * CPAD + rb * 16);
    float2* hp = (float2*)(hs + j * HPAD + rb * 16);
#pragma unroll
    for (int p = 0; p < 8; p++) {
        float2 gi = up2(acc[0][p]);
        float2 gf = up2(acc[1][p]);
        float2 gg = up2(acc[2][p]);
        float2 go = up2(acc[3][p]);
        float2 c = cp[p];
        float cn0 = sigm(gf.x) * c.x + sigm(gi.x) * tanh_(gg.x);
        float cn1 = sigm(gf.y) * c.y + sigm(gi.y) * tanh_(gg.y);
        cp[p] = make_float2(cn0, cn1);
        hp[p] = make_float2(sigm(go.x) * tanh_(cn0), sigm(go.y) * tanh_(cn1));
    }
}

__global__ void __launch_bounds__(NT, 2)
lstm_traj_kernel(const float* __restrict__ x,
                 const float* __restrict__ eWih0, const float* __restrict__ eWhh0,
                 const float* __restrict__ ebih0, const float* __restrict__ ebhh0,
                 const float* __restrict__ eWih1, const float* __restrict__ eWhh1,
                 const float* __restrict__ ebih1, const float* __restrict__ ebhh1,
                 const float* __restrict__ dWih0, const float* __restrict__ dWhh0,
                 const float* __restrict__ dbih0, const float* __restrict__ dbhh0,
                 const float* __restrict__ dWih1, const float* __restrict__ dWhh1,
                 const float* __restrict__ dbih1, const float* __restrict__ dbhh1,
                 const float* __restrict__ fcW,  const float* __restrict__ fcb,
                 float* __restrict__ out)
{
    extern __shared__ float sm[];
    uint32_t smem_u32 = (uint32_t)__cvta_generic_to_shared(sm);
    const int tid = threadIdx.x;
    const int j  = tid >> 1;            // hidden unit 0..127
    const int rb = tid & 1;             // row block: rows rb*16..rb*16+15
    const int gr0 = blockIdx.x * BR;

    // biases, combined, in registers
    float be0[4], be1[4], bd0[4], bd1[4];
#pragma unroll
    for (int g = 0; g < 4; g++) {
        int idx = g * 128 + j;
        be0[g] = ebih0[idx] + ebhh0[idx];
        be1[g] = ebih1[idx] + ebhh1[idx];
        bd0[g] = dbih0[idx] + dbhh0[idx];
        bd1[g] = dbih1[idx] + dbhh1[idx];
    }

    // zero h & c states; stage FC weights + dWih0 (once)
    for (int i = tid; i < OFF_WBUF; i += NT) sm[i] = 0.0f;
    sm[OFF_FC + tid] = fcW[tid];
    if (tid < 2) sm[OFF_FCB + tid] = fcb[tid];
    for (int i = tid; i < 1024; i += NT) sm[OFF_DW + i] = dWih0[i];
    __syncthreads();

    const float* hb0 = sm + OFF_H0 + rb * 16;
    const float* hb1 = sm + OFF_H1 + rb * 16;
    const float* xb  = sm + OFF_XS + rb * 16;

    // ======================= ENCODER =======================
#pragma unroll 1
    for (int t = 0; t < TT; t++) {
        // stage x_t transposed: xs[k][row]; 2 elems/thread; readers long gone
#pragma unroll
        for (int e = tid; e < 512; e += NT) {
            int r = e >> 4, k = e & 15;
            sm[OFF_XS + k * XPAD + r] = x[(size_t)(gr0 + r) * (TT * 16) + t * 16 + k];
        }
        // (no barrier: ih0's first-chunk barrier covers visibility)

        u64 acc[4][8];
        // layer 0
        init_acc(acc, be0);
        gemm_cp<2, XPAD>(acc, eWih0, 16, xb, sm, smem_u32, tid, j);
        gemm_cp<16, HPAD>(acc, eWhh0, 128, hb0, sm, smem_u32, tid, j);
        epilogue(acc, sm + OFF_C0, sm + OFF_H0, j, rb);
        // layer 1 (its first-chunk barrier orders epilogue0's h writes)
        init_acc(acc, be1);
        gemm_cp<16, HPAD>(acc, eWih1, 128, hb0, sm, smem_u32, tid, j);
        gemm_cp<16, HPAD>(acc, eWhh1, 128, hb1, sm, smem_u32, tid, j);
        epilogue(acc, sm + OFF_C1, sm + OFF_H1, j, rb);
        __syncthreads();   // h1 writes visible before next step's hh1 / FC
    }

    // ======================= DECODER setup =======================
    if (tid < BR) {   // dec_in = x[:, 99, :2]
        size_t base = (size_t)(gr0 + tid) * (TT * 16) + 99 * 16;
        sm[OFF_XS + tid]        = x[base + 0];
        sm[OFF_XS + XPAD + tid] = x[base + 1];
    }
    __syncthreads();

    // ======================= DECODER =======================
#pragma unroll 1
    for (int t = 0; t < TGTN; t++) {
        u64 acc[4][8];
        // layer 0: K=2 input from resident dW [512][2] + K=128 recurrent
        init_acc(acc, bd0);
#pragma unroll
        for (int k = 0; k < 2; k++) {
            const float* dw = sm + OFF_DW;
            u64 b0 = pk2(dw[(j      ) * 2 + k]);
            u64 b1 = pk2(dw[(j + 128) * 2 + k]);
            u64 b2 = pk2(dw[(j + 256) * 2 + k]);
            u64 b3 = pk2(dw[(j + 384) * 2 + k]);
            const ulonglong2* hp = (const ulonglong2*)(xb + k * XPAD);
            ulonglong2 q0 = hp[0], q1 = hp[1], q2 = hp[2], q3 = hp[3];
            u64 a[8] = {q0.x, q0.y, q1.x, q1.y, q2.x, q2.y, q3.x, q3.y};
#pragma unroll
            for (int p = 0; p < 8; p++) {
                acc[0][p] = f2fma(a[p], b0, acc[0][p]);
                acc[1][p] = f2fma(a[p], b1, acc[1][p]);
                acc[2][p] = f2fma(a[p], b2, acc[2][p]);
                acc[3][p] = f2fma(a[p], b3, acc[3][p]);
            }
        }
        gemm_cp<16, HPAD>(acc, dWhh0, 128, hb0, sm, smem_u32, tid, j);
        epilogue(acc, sm + OFF_C0, sm + OFF_H0, j, rb);
        // layer 1
        init_acc(acc, bd1);
        gemm_cp<16, HPAD>(acc, dWih1, 128, hb0, sm, smem_u32, tid, j);
        gemm_cp<16, HPAD>(acc, dWhh1, 128, hb1, sm, smem_u32, tid, j);
        epilogue(acc, sm + OFF_C1, sm + OFF_H1, j, rb);
        __syncthreads();   // h1 ready for FC

        // FC + output + feedback
        if (tid < 2 * BR) {
            int r = tid >> 1;
            int o = tid & 1;
            float s = sm[OFF_FCB + o];
            const float* fw = sm + OFF_FC + o * 128;
            const float* hv = sm + OFF_H1 + r;
#pragma unroll 8
            for (int jj = 0; jj < 128; jj++) s += hv[jj * HPAD] * fw[jj];
            out[((size_t)(gr0 + r) * TGTN + t) * 2 + o] = s;
            sm[OFF_XS + o * XPAD + r] = s;
        }
        __syncthreads();   // feedback visible before next step's K=2 accum
    }
}

extern "C" void kernel_launch(void* const* d_in, const int* in_sizes, int n_in,
                              void* d_out, int out_size)
{
    const float* x     = (const float*)d_in[0];
    const float* eWih0 = (const float*)d_in[2];
    const float* eWhh0 = (const float*)d_in[3];
    const float* ebih0 = (const float*)d_in[4];
    const float* ebhh0 = (const float*)d_in[5];
    const float* eWih1 = (const float*)d_in[6];
    const float* eWhh1 = (const float*)d_in[7];
    const float* ebih1 = (const float*)d_in[8];
    const float* ebhh1 = (const float*)d_in[9];
    const float* dWih0 = (const float*)d_in[10];
    const float* dWhh0 = (const float*)d_in[11];
    const float* dbih0 = (const float*)d_in[12];
    const float* dbhh0 = (const float*)d_in[13];
    const float* dWih1 = (const float*)d_in[14];
    const float* dWhh1 = (const float*)d_in[15];
    const float* dbih1 = (const float*)d_in[16];
    const float* dbhh1 = (const float*)d_in[17];
    const float* fcW   = (const float*)d_in[18];
    const float* fcb   = (const float*)d_in[19];
    float* out = (float*)d_out;

    cudaFuncSetAttribute(lstm_traj_kernel,
                         cudaFuncAttributeMaxDynamicSharedMemorySize, SMEM_BYTES);

    lstm_traj_kernel<<<BB / BR, NT, SMEM_BYTES>>>(
        x, eWih0, eWhh0, ebih0, ebhh0, eWih1, eWhh1, ebih1, ebhh1,
        dWih0, dWhh0, dbih0, dbhh0, dWih1, dWhh1, dbih1, dbhh1,
        fcW, fcb, out);
}

// round 11
// speedup vs baseline: 2.2991x; 2.2991x over previous
#include <cuda_runtime.h>
#include <cstdint>

// Problem constants
#define BB    8192
#define TT    100
#define TGTN  60

#define NT    256     // threads per CTA (8 warps)
#define BR    32      // batch rows per CTA
#define HPAD  36      // h row stride (floats)
#define CPAD  32      // c row stride (floats)
#define XPAD  32      // x/feedback row stride (floats)
#define CHUNKF 4096   // one weight buffer: [512 rows][8 k] floats (16KB)

// Shared layout (float offsets, all 16B-aligned)
#define OFF_H0   0                 // [128][36]
#define OFF_H1   4608              // [128][36]
#define OFF_C0   9216              // [128][32]
#define OFF_C1   13312             // [128][32]
#define OFF_WBUF 17408             // 2 x [512][8]
#define OFF_XS   25600             // [16][32]
#define OFF_FC   26112             // fcW [2][128]
#define OFF_FCB  26368             // fcb [2] + pad
#define OFF_DW   26372             // dWih0 native [512][2]
#define SMEM_FLOATS 27396
#define SMEM_BYTES  (SMEM_FLOATS*4)   // 109,584 B -> 2 CTAs/SM

// Packed-weight scratch: 6 big matrices [16 chunks][512][8] + eWih0 [2 chunks][512][8]
#define PACK_M   65536             // floats per big matrix
#define PACK_TOT (6*PACK_M + 2*4096)
__device__ float g_wpack[PACK_TOT];

typedef unsigned long long u64;

// ---- packed f32x2 helpers ----
__device__ __forceinline__ u64 pk2(float x) {
    u64 r; asm("mov.b64 %0, {%1, %1};" : "=l"(r) : "f"(x)); return r;
}
__device__ __forceinline__ u64 f2fma(u64 a, u64 b, u64 c) {
    u64 d; asm("fma.rn.f32x2 %0, %1, %2, %3;" : "=l"(d) : "l"(a), "l"(b), "l"(c)); return d;
}
__device__ __forceinline__ float2 up2(u64 v) {
    float2 f; asm("mov.b64 {%0, %1}, %2;" : "=f"(f.x), "=f"(f.y) : "l"(v)); return f;
}

// ---- activations ----
__device__ __forceinline__ float sigm(float x) {
    return __fdividef(1.0f, 1.0f + __expf(-x));
}
__device__ __forceinline__ float tanh_(float x) {
    float a = fabsf(x);
    float e = __expf(-2.0f * a);
    float t = __fdividef(1.0f - e, 1.0f + e);
    return copysignf(t, x);
}

// ---- prologue: repack weights chunk-major ----
__global__ void repack_kernel(const float* __restrict__ eWhh0, const float* __restrict__ eWih1,
                              const float* __restrict__ eWhh1, const float* __restrict__ dWhh0,
                              const float* __restrict__ dWih1, const float* __restrict__ dWhh1,
                              const float* __restrict__ eWih0)
{
    int idx = blockIdx.x * 256 + threadIdx.x;
    if (idx < 6 * PACK_M) {
        int m   = idx >> 16;
        int rem = idx & (PACK_M - 1);
        int c = rem >> 12;
        int r = (rem >> 3) & 511;
        int k = rem & 7;
        const float* W = m == 0 ? eWhh0 : m == 1 ? eWih1 : m == 2 ? eWhh1
                       : m == 3 ? dWhh0 : m == 4 ? dWih1 : dWhh1;
        g_wpack[idx] = W[r * 128 + c * 8 + k];
    } else if (idx < PACK_TOT) {
        int rem = idx - 6 * PACK_M;
        int c = rem >> 12;
        int r = (rem >> 3) & 511;
        int k = rem & 7;
        g_wpack[idx] = eWih0[r * 16 + c * 8 + k];
    }
}

__device__ __forceinline__ void init_acc(u64 acc[4][8], const float b[4])
{
#pragma unroll
    for (int g = 0; g < 4; g++) {
        u64 bb = pk2(b[g]);
#pragma unroll
        for (int p = 0; p < 8; p++) acc[g][p] = bb;
    }
}

// ---- streamed GEMM over K = NCH*8 from PACKED weights.
//      Each chunk is a contiguous 16KB block [512][8]; cp.async 8B units,
//      coalesced source, XOR-swizzled dest: word(r,k) = r*8 + (k ^ 2*((r>>2)&3)).
//      Double buffer, one barrier per chunk, depth-1 prefetch. ----
template<int NCH, int STRIDE>
__device__ __forceinline__ void gemm_cp(u64 acc[4][8],
                                        const float* __restrict__ Wp,   // packed base
                                        const float* __restrict__ hb,
                                        const float* __restrict__ sm,
                                        uint32_t smem_u32,
                                        const uint32_t doff[8],         // per-thread swizzled dest byte offsets
                                        int tid, int j)
{
    const int kx = ((j >> 2) & 3) << 1;   // k-xor for this thread's gate rows

    auto issue = [&](int c) {
        uint32_t dbase = smem_u32 + (uint32_t)((OFF_WBUF + (c & 1) * CHUNKF) * 4);
        const float* src = Wp + c * CHUNKF + tid * 2;
#pragma unroll
        for (int i = 0; i < 8; i++)
            asm volatile("cp.async.ca.shared.global [%0], [%1], 8;"
                         :: "r"(dbase + doff[i]), "l"(src + i * 512));
        asm volatile("cp.async.commit_group;" ::: "memory");
    };

    issue(0);
#pragma unroll 1
    for (int c = 0; c < NCH; c++) {
        asm volatile("cp.async.wait_group 0;" ::: "memory");
        __syncthreads();                 // chunk c visible; other buffer's readers done
        if (c + 1 < NCH) issue(c + 1);
        const float* wb = sm + OFF_WBUF + (c & 1) * CHUNKF;
        const float* hc = hb + c * 8 * STRIDE;
#pragma unroll
        for (int k = 0; k < 8; k++) {
            int kk = k ^ kx;
            u64 b0 = pk2(wb[(j      ) * 8 + kk]);
            u64 b1 = pk2(wb[(j + 128) * 8 + kk]);
            u64 b2 = pk2(wb[(j + 256) * 8 + kk]);
            u64 b3 = pk2(wb[(j + 384) * 8 + kk]);
            const ulonglong2* hp = (const ulonglong2*)(hc + k * STRIDE);
            ulonglong2 q0 = hp[0], q1 = hp[1], q2 = hp[2], q3 = hp[3];
            u64 a[8] = {q0.x, q0.y, q1.x, q1.y, q2.x, q2.y, q3.x, q3.y};
#pragma unroll
            for (int p = 0; p < 8; p++) {
                acc[0][p] = f2fma(a[p], b0, acc[0][p]);
                acc[1][p] = f2fma(a[p], b1, acc[1][p]);
                acc[2][p] = f2fma(a[p], b2, acc[2][p]);
                acc[3][p] = f2fma(a[p], b3, acc[3][p]);
            }
        }
    }
    __syncthreads();   // protect h/x rewrites after this gemm from stragglers
}

// ---- LSTM pointwise epilogue: unit j, rows rb*16..rb*16+15; c in smem ----
__device__ __forceinline__ void epilogue(u64 acc[4][8],
                                         float* __restrict__ cs,
                                         float* __restrict__ hs,
                                         int j, int rb)
{
    float2* cp = (float2*)(cs + j * CPAD + rb * 16);
    float2* hp = (float2*)(hs + j * HPAD + rb * 16);
#pragma unroll
    for (int p = 0; p < 8; p++) {
        float2 gi = up2(acc[0][p]);
        float2 gf = up2(acc[1][p]);
        float2 gg = up2(acc[2][p]);
        float2 go = up2(acc[3][p]);
        float2 c = cp[p];
        float cn0 = sigm(gf.x) * c.x + sigm(gi.x) * tanh_(gg.x);
        float cn1 = sigm(gf.y) * c.y + sigm(gi.y) * tanh_(gg.y);
        cp[p] = make_float2(cn0, cn1);
        hp[p] = make_float2(sigm(go.x) * tanh_(cn0), sigm(go.y) * tanh_(cn1));
    }
}

__global__ void __launch_bounds__(NT, 2)
lstm_traj_kernel(const float* __restrict__ x,
                 const float* __restrict__ ebih0, const float* __restrict__ ebhh0,
                 const float* __restrict__ ebih1, const float* __restrict__ ebhh1,
                 const float* __restrict__ dWih0,
                 const float* __restrict__ dbih0, const float* __restrict__ dbhh0,
                 const float* __restrict__ dbih1, const float* __restrict__ dbhh1,
                 const float* __restrict__ fcW,  const float* __restrict__ fcb,
                 float* __restrict__ out)
{
    extern __shared__ float sm[];
    uint32_t smem_u32 = (uint32_t)__cvta_generic_to_shared(sm);
    const int tid = threadIdx.x;
    const int j  = tid >> 1;            // hidden unit 0..127
    const int rb = tid & 1;             // row block: rows rb*16..rb*16+15
    const int gr0 = blockIdx.x * BR;

    // precompute cp.async swizzled dest byte offsets (8B unit u = tid + 256*i)
    uint32_t doff[8];
#pragma unroll
    for (int i = 0; i < 8; i++) {
        int u = tid + 256 * i;
        int r = u >> 2;
        int h = u & 3;
        doff[i] = (uint32_t)((r * 8 + ((h ^ ((r >> 2) & 3)) << 1)) * 4);
    }

    // biases, combined, in registers
    float be0[4], be1[4], bd0[4], bd1[4];
#pragma unroll
    for (int g = 0; g < 4; g++) {
        int idx = g * 128 + j;
        be0[g] = ebih0[idx] + ebhh0[idx];
        be1[g] = ebih1[idx] + ebhh1[idx];
        bd0[g] = dbih0[idx] + dbhh0[idx];
        bd1[g] = dbih1[idx] + dbhh1[idx];
    }

    // zero h & c states; stage FC weights + dWih0 (once)
    for (int i = tid; i < OFF_WBUF; i += NT) sm[i] = 0.0f;
    sm[OFF_FC + tid] = fcW[tid];
    if (tid < 2) sm[OFF_FCB + tid] = fcb[tid];
    for (int i = tid; i < 1024; i += NT) sm[OFF_DW + i] = dWih0[i];
    __syncthreads();

    const float* hb0 = sm + OFF_H0 + rb * 16;
    const float* hb1 = sm + OFF_H1 + rb * 16;
    const float* xb  = sm + OFF_XS + rb * 16;

    // packed weight bases
    const float* pWhh0  = g_wpack + 0 * PACK_M;
    const float* pWih1  = g_wpack + 1 * PACK_M;
    const float* pWhh1  = g_wpack + 2 * PACK_M;
    const float* pdWhh0 = g_wpack + 3 * PACK_M;
    const float* pdWih1 = g_wpack + 4 * PACK_M;
    const float* pdWhh1 = g_wpack + 5 * PACK_M;
    const float* pWih0  = g_wpack + 6 * PACK_M;

    // ======================= ENCODER =======================
#pragma unroll 1
    for (int t = 0; t < TT; t++) {
        // stage x_t transposed: xs[k][row]; readers long gone
#pragma unroll
        for (int e = tid; e < 512; e += NT) {
            int r = e >> 4, k = e & 15;
            sm[OFF_XS + k * XPAD + r] = x[(size_t)(gr0 + r) * (TT * 16) + t * 16 + k];
        }
        // (no barrier: ih0's first-chunk barrier covers visibility)

        u64 acc[4][8];
        // layer 0
        init_acc(acc, be0);
        gemm_cp<2, XPAD>(acc, pWih0, xb, sm, smem_u32, doff, tid, j);
        gemm_cp<16, HPAD>(acc, pWhh0, hb0, sm, smem_u32, doff, tid, j);
        epilogue(acc, sm + OFF_C0, sm + OFF_H0, j, rb);
        // layer 1 (its first-chunk barrier orders epilogue0's h writes)
        init_acc(acc, be1);
        gemm_cp<16, HPAD>(acc, pWih1, hb0, sm, smem_u32, doff, tid, j);
        gemm_cp<16, HPAD>(acc, pWhh1, hb1, sm, smem_u32, doff, tid, j);
        epilogue(acc, sm + OFF_C1, sm + OFF_H1, j, rb);
        __syncthreads();   // h1 writes visible before next step's hh1 / FC
    }

    // ======================= DECODER setup =======================
    if (tid < BR) {   // dec_in = x[:, 99, :2]
        size_t base = (size_t)(gr0 + tid) * (TT * 16) + 99 * 16;
        sm[OFF_XS + tid]        = x[base + 0];
        sm[OFF_XS + XPAD + tid] = x[base + 1];
    }
    __syncthreads();

    // ======================= DECODER =======================
#pragma unroll 1
    for (int t = 0; t < TGTN; t++) {
        u64 acc[4][8];
        // layer 0: K=2 input from resident dW [512][2] + K=128 recurrent
        init_acc(acc, bd0);
#pragma unroll
        for (int k = 0; k < 2; k++) {
            const float* dw = sm + OFF_DW;
            u64 b0 = pk2(dw[(j      ) * 2 + k]);
            u64 b1 = pk2(dw[(j + 128) * 2 + k]);
            u64 b2 = pk2(dw[(j + 256) * 2 + k]);
            u64 b3 = pk2(dw[(j + 384) * 2 + k]);
            const ulonglong2* hp = (const ulonglong2*)(xb + k * XPAD);
            ulonglong2 q0 = hp[0], q1 = hp[1], q2 = hp[2], q3 = hp[3];
            u64 a[8] = {q0.x, q0.y, q1.x, q1.y, q2.x, q2.y, q3.x, q3.y};
#pragma unroll
            for (int p = 0; p < 8; p++) {
                acc[0][p] = f2fma(a[p], b0, acc[0][p]);
                acc[1][p] = f2fma(a[p], b1, acc[1][p]);
                acc[2][p] = f2fma(a[p], b2, acc[2][p]);
                acc[3][p] = f2fma(a[p], b3, acc[3][p]);
            }
        }
        gemm_cp<16, HPAD>(acc, pdWhh0, hb0, sm, smem_u32, doff, tid, j);
        epilogue(acc, sm + OFF_C0, sm + OFF_H0, j, rb);
        // layer 1
        init_acc(acc, bd1);
        gemm_cp<16, HPAD>(acc, pdWih1, hb0, sm, smem_u32, doff, tid, j);
        gemm_cp<16, HPAD>(acc, pdWhh1, hb1, sm, smem_u32, doff, tid, j);
        epilogue(acc, sm + OFF_C1, sm + OFF_H1, j, rb);
        __syncthreads();   // h1 ready for FC

        // FC + output + feedback
        if (tid < 2 * BR) {
            int r = tid >> 1;
            int o = tid & 1;
            float s = sm[OFF_FCB + o];
            const float* fw = sm + OFF_FC + o * 128;
            const float* hv = sm + OFF_H1 + r;
#pragma unroll 8
            for (int jj = 0; jj < 128; jj++) s += hv[jj * HPAD] * fw[jj];
            out[((size_t)(gr0 + r) * TGTN + t) * 2 + o] = s;
            sm[OFF_XS + o * XPAD + r] = s;
        }
        __syncthreads();   // feedback visible before next step's K=2 accum
    }
}

extern "C" void kernel_launch(void* const* d_in, const int* in_sizes, int n_in,
                              void* d_out, int out_size)
{
    const float* x     = (const float*)d_in[0];
    const float* eWih0 = (const float*)d_in[2];
    const float* eWhh0 = (const float*)d_in[3];
    const float* ebih0 = (const float*)d_in[4];
    const float* ebhh0 = (const float*)d_in[5];
    const float* eWih1 = (const float*)d_in[6];
    const float* eWhh1 = (const float*)d_in[7];
    const float* ebih1 = (const float*)d_in[8];
    const float* ebhh1 = (const float*)d_in[9];
    const float* dWih0 = (const float*)d_in[10];
    const float* dWhh0 = (const float*)d_in[11];
    const float* dbih0 = (const float*)d_in[12];
    const float* dbhh0 = (const float*)d_in[13];
    const float* dWih1 = (const float*)d_in[14];
    const float* dWhh1 = (const float*)d_in[15];
    const float* dbih1 = (const float*)d_in[16];
    const float* dbhh1 = (const float*)d_in[17];
    const float* fcW   = (const float*)d_in[18];
    const float* fcb   = (const float*)d_in[19];
    float* out = (float*)d_out;

    // 1) repack weights chunk-major
    repack_kernel<<<(PACK_TOT + 255) / 256, 256>>>(
        eWhh0, eWih1, eWhh1, dWhh0, dWih1, dWhh1, eWih0);

    // 2) main kernel
    cudaFuncSetAttribute(lstm_traj_kernel,
                         cudaFuncAttributeMaxDynamicSharedMemorySize, SMEM_BYTES);
    lstm_traj_kernel<<<BB / BR, NT, SMEM_BYTES>>>(
        x, ebih0, ebhh0, ebih1, ebhh1,
        dWih0, dbih0, dbhh0, dbih1, dbhh1,
        fcW, fcb, out);
}

// round 12
// speedup vs baseline: 2.7155x; 1.1811x over previous
#include <cuda_runtime.h>
#include <cstdint>

// Problem constants
#define BB    8192
#define TT    100
#define TGTN  60

#define NT    256     // threads per CTA (8 warps)
#define BR    32      // batch rows per CTA
#define HPAD  36      // h row stride (floats)
#define CPAD  32      // c row stride (floats)
#define XPAD  32      // x/feedback row stride (floats)
#define CHUNKF 4096   // one weight buffer: [128 j][8 kk][4 g] floats (16KB)

// Shared layout (float offsets, all 16B-aligned)
#define OFF_H0   0                 // [128][36]
#define OFF_H1   4608              // [128][36]
#define OFF_C0   9216              // [128][32]
#define OFF_C1   13312             // [128][32]
#define OFF_WBUF 17408             // 2 x CHUNKF
#define OFF_XS   25600             // [16][32]
#define OFF_FC   26112             // fcW [2][128]
#define OFF_FCB  26368             // fcb [2] + pad
#define OFF_DW   26372             // dWih0 native [512][2]
#define SMEM_FLOATS 27396
#define SMEM_BYTES  (SMEM_FLOATS*4)   // 109,584 B -> 2 CTAs/SM

// Packed-weight scratch: 6 big matrices [16 chunks][128][8][4] + eWih0 [2 chunks][128][8][4]
#define PACK_M   65536             // floats per big matrix
#define PACK_TOT (6*PACK_M + 2*4096)
__device__ float g_wpack[PACK_TOT];

typedef unsigned long long u64;

// ---- packed f32x2 helpers ----
__device__ __forceinline__ u64 pk2(float x) {
    u64 r; asm("mov.b64 %0, {%1, %1};" : "=l"(r) : "f"(x)); return r;
}
__device__ __forceinline__ u64 f2fma(u64 a, u64 b, u64 c) {
    u64 d; asm("fma.rn.f32x2 %0, %1, %2, %3;" : "=l"(d) : "l"(a), "l"(b), "l"(c)); return d;
}
__device__ __forceinline__ float2 up2(u64 v) {
    float2 f; asm("mov.b64 {%0, %1}, %2;" : "=f"(f.x), "=f"(f.y) : "l"(v)); return f;
}

// ---- activations ----
__device__ __forceinline__ float sigm(float x) {
    return __fdividef(1.0f, 1.0f + __expf(-x));
}
__device__ __forceinline__ float tanh_(float x) {
    float a = fabsf(x);
    float e = __expf(-2.0f * a);
    float t = __fdividef(1.0f - e, 1.0f + e);
    return copysignf(t, x);
}

// ---- prologue: repack weights into gate-interleaved, bank-swizzled,
//      chunk-major layout: pack[c][j][kk][g] = W[(g*128+j)][c*8 + (kk ^ (j&7))] ----
__global__ void repack_kernel(const float* __restrict__ eWhh0, const float* __restrict__ eWih1,
                              const float* __restrict__ eWhh1, const float* __restrict__ dWhh0,
                              const float* __restrict__ dWih1, const float* __restrict__ dWhh1,
                              const float* __restrict__ eWih0)
{
    int idx = blockIdx.x * 256 + threadIdx.x;
    if (idx < 6 * PACK_M) {
        int m   = idx >> 16;
        int rem = idx & (PACK_M - 1);
        int c  = rem >> 12;
        int j  = (rem >> 5) & 127;
        int kk = (rem >> 2) & 7;
        int g  = rem & 3;
        int k  = kk ^ (j & 7);
        const float* W = m == 0 ? eWhh0 : m == 1 ? eWih1 : m == 2 ? eWhh1
                       : m == 3 ? dWhh0 : m == 4 ? dWih1 : dWhh1;
        g_wpack[idx] = W[(g * 128 + j) * 128 + c * 8 + k];
    } else if (idx < PACK_TOT) {
        int rem = idx - 6 * PACK_M;
        int c  = rem >> 12;
        int j  = (rem >> 5) & 127;
        int kk = (rem >> 2) & 7;
        int g  = rem & 3;
        int k  = kk ^ (j & 7);
        g_wpack[rem + 6 * PACK_M] = eWih0[(g * 128 + j) * 16 + c * 8 + k];
    }
}

__device__ __forceinline__ void init_acc(u64 acc[4][8], const float b[4])
{
#pragma unroll
    for (int g = 0; g < 4; g++) {
        u64 bb = pk2(b[g]);
#pragma unroll
        for (int p = 0; p < 8; p++) acc[g][p] = bb;
    }
}

// ---- streamed GEMM over K = NCH*8 from PACKED gate-interleaved weights.
//      Chunk = contiguous 16KB; cp.async.cg 16B straight copy (swizzle is
//      pre-baked in global). Read: 1 LDS.128 per k via XOR-folded address.
//      Double buffer, one barrier per chunk, depth-1 prefetch. ----
template<int NCH, int STRIDE>
__device__ __forceinline__ void gemm_cp(u64 acc[4][8],
                                        const float* __restrict__ Wp,   // packed base
                                        const float* __restrict__ hb,
                                        const char* __restrict__ smc,   // shared base (bytes)
                                        uint32_t smem_u32, int tid, int j)
{
    const uint32_t jx16 = (uint32_t)((j & 7) << 4);

    auto issue = [&](int c) {
        uint32_t dst = smem_u32 + (uint32_t)((OFF_WBUF + (c & 1) * CHUNKF) * 4 + tid * 16);
        const float* src = Wp + c * CHUNKF + tid * 4;
#pragma unroll
        for (int i = 0; i < 4; i++)
            asm volatile("cp.async.cg.shared.global [%0], [%1], 16;"
                         :: "r"(dst + (uint32_t)(i * 4096)), "l"(src + i * 1024));
        asm volatile("cp.async.commit_group;" ::: "memory");
    };

    issue(0);
#pragma unroll 1
    for (int c = 0; c < NCH; c++) {
        asm volatile("cp.async.wait_group 0;" ::: "memory");
        __syncthreads();                 // chunk c visible; other buffer's readers done
        if (c + 1 < NCH) issue(c + 1);
        // w base for this thread: all low 7 bits of (OFF_WBUF+buf+j*32)*4 are 0 -> XOR-safe
        const uint32_t wbx = (uint32_t)((OFF_WBUF + (c & 1) * CHUNKF + j * 32) * 4) ^ jx16;
        const float* hc = hb + c * 8 * STRIDE;
#pragma unroll
        for (int k = 0; k < 8; k++) {
            float4 wv = *(const float4*)(smc + (wbx ^ (uint32_t)(k << 4)));
            u64 b0 = pk2(wv.x);
            u64 b1 = pk2(wv.y);
            u64 b2 = pk2(wv.z);
            u64 b3 = pk2(wv.w);
            const ulonglong2* hp = (const ulonglong2*)(hc + k * STRIDE);
            ulonglong2 q0 = hp[0], q1 = hp[1], q2 = hp[2], q3 = hp[3];
            u64 a[8] = {q0.x, q0.y, q1.x, q1.y, q2.x, q2.y, q3.x, q3.y};
#pragma unroll
            for (int p = 0; p < 8; p++) {
                acc[0][p] = f2fma(a[p], b0, acc[0][p]);
                acc[1][p] = f2fma(a[p], b1, acc[1][p]);
                acc[2][p] = f2fma(a[p], b2, acc[2][p]);
                acc[3][p] = f2fma(a[p], b3, acc[3][p]);
            }
        }
    }
    __syncthreads();   // protect wbuf/h/x reuse after this gemm
}

// ---- LSTM pointwise epilogue: unit j, rows rb*16..rb*16+15; c in smem ----
__device__ __forceinline__ void epilogue(u64 acc[4][8],
                                         float* __restrict__ cs,
                                         float* __restrict__ hs,
                                         int j, int rb)
{
    float2* cp = (float2*)(cs + j * CPAD + rb * 16);
    float2* hp = (float2*)(hs + j * HPAD + rb * 16);
#pragma unroll
    for (int p = 0; p < 8; p++) {
        float2 gi = up2(acc[0][p]);
        float2 gf = up2(acc[1][p]);
        float2 gg = up2(acc[2][p]);
        float2 go = up2(acc[3][p]);
        float2 c = cp[p];
        float cn0 = sigm(gf.x) * c.x + sigm(gi.x) * tanh_(gg.x);
        float cn1 = sigm(gf.y) * c.y + sigm(gi.y) * tanh_(gg.y);
        cp[p] = make_float2(cn0, cn1);
        hp[p] = make_float2(sigm(go.x) * tanh_(cn0), sigm(go.y) * tanh_(cn1));
    }
}

__global__ void __launch_bounds__(NT, 2)
lstm_traj_kernel(const float* __restrict__ x,
                 const float* __restrict__ ebih0, const float* __restrict__ ebhh0,
                 const float* __restrict__ ebih1, const float* __restrict__ ebhh1,
                 const float* __restrict__ dWih0,
                 const float* __restrict__ dbih0, const float* __restrict__ dbhh0,
                 const float* __restrict__ dbih1, const float* __restrict__ dbhh1,
                 const float* __restrict__ fcW,  const float* __restrict__ fcb,
                 float* __restrict__ out)
{
    extern __shared__ float sm[];
    const char* smc = (const char*)sm;
    uint32_t smem_u32 = (uint32_t)__cvta_generic_to_shared(sm);
    const int tid = threadIdx.x;
    const int j  = tid >> 1;            // hidden unit 0..127
    const int rb = tid & 1;             // row block: rows rb*16..rb*16+15
    const int gr0 = blockIdx.x * BR;

    // biases, combined, in registers
    float be0[4], be1[4], bd0[4], bd1[4];
#pragma unroll
    for (int g = 0; g < 4; g++) {
        int idx = g * 128 + j;
        be0[g] = ebih0[idx] + ebhh0[idx];
        be1[g] = ebih1[idx] + ebhh1[idx];
        bd0[g] = dbih0[idx] + dbhh0[idx];
        bd1[g] = dbih1[idx] + dbhh1[idx];
    }

    // zero h & c states; stage FC weights + dWih0 (once)
    for (int i = tid; i < OFF_WBUF; i += NT) sm[i] = 0.0f;
    sm[OFF_FC + tid] = fcW[tid];
    if (tid < 2) sm[OFF_FCB + tid] = fcb[tid];
    for (int i = tid; i < 1024; i += NT) sm[OFF_DW + i] = dWih0[i];
    __syncthreads();

    const float* hb0 = sm + OFF_H0 + rb * 16;
    const float* hb1 = sm + OFF_H1 + rb * 16;
    const float* xb  = sm + OFF_XS + rb * 16;

    // packed weight bases
    const float* pWhh0  = g_wpack + 0 * PACK_M;
    const float* pWih1  = g_wpack + 1 * PACK_M;
    const float* pWhh1  = g_wpack + 2 * PACK_M;
    const float* pdWhh0 = g_wpack + 3 * PACK_M;
    const float* pdWih1 = g_wpack + 4 * PACK_M;
    const float* pdWhh1 = g_wpack + 5 * PACK_M;
    const float* pWih0  = g_wpack + 6 * PACK_M;

    // ======================= ENCODER =======================
#pragma unroll 1
    for (int t = 0; t < TT; t++) {
        // stage x_t transposed: xs[k][row]; readers long gone
#pragma unroll
        for (int e = tid; e < 512; e += NT) {
            int r = e >> 4, k = e & 15;
            sm[OFF_XS + k * XPAD + r] = x[(size_t)(gr0 + r) * (TT * 16) + t * 16 + k];
        }
        // (no barrier: ih0's first-chunk barrier covers visibility)

        u64 acc[4][8];
        // layer 0
        init_acc(acc, be0);
        gemm_cp<2, XPAD>(acc, pWih0, xb, smc, smem_u32, tid, j);
        gemm_cp<16, HPAD>(acc, pWhh0, hb0, smc, smem_u32, tid, j);
        epilogue(acc, sm + OFF_C0, sm + OFF_H0, j, rb);
        // layer 1 (its first-chunk barrier orders epilogue0's h writes)
        init_acc(acc, be1);
        gemm_cp<16, HPAD>(acc, pWih1, hb0, smc, smem_u32, tid, j);
        gemm_cp<16, HPAD>(acc, pWhh1, hb1, smc, smem_u32, tid, j);
        epilogue(acc, sm + OFF_C1, sm + OFF_H1, j, rb);
        __syncthreads();   // h1 writes visible before next step's hh1 / FC
    }

    // ======================= DECODER setup =======================
    if (tid < BR) {   // dec_in = x[:, 99, :2]
        size_t base = (size_t)(gr0 + tid) * (TT * 16) + 99 * 16;
        sm[OFF_XS + tid]        = x[base + 0];
        sm[OFF_XS + XPAD + tid] = x[base + 1];
    }
    __syncthreads();

    // ======================= DECODER =======================
#pragma unroll 1
    for (int t = 0; t < TGTN; t++) {
        u64 acc[4][8];
        // layer 0: K=2 input from resident dW [512][2] + K=128 recurrent
        init_acc(acc, bd0);
#pragma unroll
        for (int k = 0; k < 2; k++) {
            const float* dw = sm + OFF_DW;
            u64 b0 = pk2(dw[(j      ) * 2 + k]);
            u64 b1 = pk2(dw[(j + 128) * 2 + k]);
            u64 b2 = pk2(dw[(j + 256) * 2 + k]);
            u64 b3 = pk2(dw[(j + 384) * 2 + k]);
            const ulonglong2* hp = (const ulonglong2*)(xb + k * XPAD);
            ulonglong2 q0 = hp[0], q1 = hp[1], q2 = hp[2], q3 = hp[3];
            u64 a[8] = {q0.x, q0.y, q1.x, q1.y, q2.x, q2.y, q3.x, q3.y};
#pragma unroll
            for (int p = 0; p < 8; p++) {
                acc[0][p] = f2fma(a[p], b0, acc[0][p]);
                acc[1][p] = f2fma(a[p], b1, acc[1][p]);
                acc[2][p] = f2fma(a[p], b2, acc[2][p]);
                acc[3][p] = f2fma(a[p], b3, acc[3][p]);
            }
        }
        gemm_cp<16, HPAD>(acc, pdWhh0, hb0, smc, smem_u32, tid, j);
        epilogue(acc, sm + OFF_C0, sm + OFF_H0, j, rb);
        // layer 1
        init_acc(acc, bd1);
        gemm_cp<16, HPAD>(acc, pdWih1, hb0, smc, smem_u32, tid, j);
        gemm_cp<16, HPAD>(acc, pdWhh1, hb1, smc, smem_u32, tid, j);
        epilogue(acc, sm + OFF_C1, sm + OFF_H1, j, rb);
        __syncthreads();   // h1 ready for FC

        // FC + output + feedback
        if (tid < 2 * BR) {
            int r = tid >> 1;
            int o = tid & 1;
            float s = sm[OFF_FCB + o];
            const float* fw = sm + OFF_FC + o * 128;
            const float* hv = sm + OFF_H1 + r;
#pragma unroll 8
            for (int jj = 0; jj < 128; jj++) s += hv[jj * HPAD] * fw[jj];
            out[((size_t)(gr0 + r) * TGTN + t) * 2 + o] = s;
            sm[OFF_XS + o * XPAD + r] = s;
        }
        __syncthreads();   // feedback visible before next step's K=2 accum
    }
}

extern "C" void kernel_launch(void* const* d_in, const int* in_sizes, int n_in,
                              void* d_out, int out_size)
{
    const float* x     = (const float*)d_in[0];
    const float* eWih0 = (const float*)d_in[2];
    const float* eWhh0 = (const float*)d_in[3];
    const float* ebih0 = (const float*)d_in[4];
    const float* ebhh0 = (const float*)d_in[5];
    const float* eWih1 = (const float*)d_in[6];
    const float* eWhh1 = (const float*)d_in[7];
    const float* ebih1 = (const float*)d_in[8];
    const float* ebhh1 = (const float*)d_in[9];
    const float* dWih0 = (const float*)d_in[10];
    const float* dWhh0 = (const float*)d_in[11];
    const float* dbih0 = (const float*)d_in[12];
    const float* dbhh0 = (const float*)d_in[13];
    const float* dWih1 = (const float*)d_in[14];
    const float* dWhh1 = (const float*)d_in[15];
    const float* dbih1 = (const float*)d_in[16];
    const float* dbhh1 = (const float*)d_in[17];
    const float* fcW   = (const float*)d_in[18];
    const float* fcb   = (const float*)d_in[19];
    float* out = (float*)d_out;

    // 1) repack weights gate-interleaved + bank-swizzled, chunk-major
    repack_kernel<<<(PACK_TOT + 255) / 256, 256>>>(
        eWhh0, eWih1, eWhh1, dWhh0, dWih1, dWhh1, eWih0);

    // 2) main kernel
    cudaFuncSetAttribute(lstm_traj_kernel,
                         cudaFuncAttributeMaxDynamicSharedMemorySize, SMEM_BYTES);
    lstm_traj_kernel<<<BB / BR, NT, SMEM_BYTES>>>(
        x, ebih0, ebhh0, ebih1, ebhh1,
        dWih0, dbih0, dbhh0, dbih1, dbhh1,
        fcW, fcb, out);
}

// round 13
// speedup vs baseline: 3.1322x; 1.1535x over previous
#include <cuda_runtime.h>
#include <cstdint>

// Problem constants
#define BB    8192
#define TT    100
#define TGTN  60

#define NT    256     // threads per CTA (8 warps)
#define GRID  296     // 2 x 148 SMs -> perfectly balanced 2 CTAs/SM
#define NBIG  200     // first 200 CTAs take 28 rows, rest 27 (200*28+96*27=8192)
#define BRMX  28      // max rows per CTA
#define RH    14      // rows per half (rb)
#define HPAD  36      // h row stride (floats)
#define CPAD  32      // c row stride (floats)
#define XPAD  32      // x/feedback row stride (floats)
#define CHUNKF 4096   // one weight buffer: [128 j][8 kk][4 g] floats (16KB)

// Shared layout (float offsets, all 16B-aligned) -- identical to R12
#define OFF_H0   0                 // [128][36] (slots 0..13,16..29 used)
#define OFF_H1   4608
#define OFF_C0   9216              // [128][32]
#define OFF_C1   13312
#define OFF_WBUF 17408             // 2 x CHUNKF
#define OFF_XS   25600             // [16][32]
#define OFF_FC   26112             // fcW [2][128]
#define OFF_FCB  26368             // fcb [2] + pad
#define OFF_DW   26372             // dWih0 native [512][2]
#define SMEM_FLOATS 27396
#define SMEM_BYTES  (SMEM_FLOATS*4)   // 109,584 B -> 2 CTAs/SM

// Packed-weight scratch: 6 big matrices [16 chunks][128][8][4] + eWih0 [2 chunks][128][8][4]
#define PACK_M   65536
#define PACK_TOT (6*PACK_M + 2*4096)
__device__ float g_wpack[PACK_TOT];

typedef unsigned long long u64;

// ---- packed f32x2 helpers ----
__device__ __forceinline__ u64 pk2(float x) {
    u64 r; asm("mov.b64 %0, {%1, %1};" : "=l"(r) : "f"(x)); return r;
}
__device__ __forceinline__ u64 f2fma(u64 a, u64 b, u64 c) {
    u64 d; asm("fma.rn.f32x2 %0, %1, %2, %3;" : "=l"(d) : "l"(a), "l"(b), "l"(c)); return d;
}
__device__ __forceinline__ float2 up2(u64 v) {
    float2 f; asm("mov.b64 {%0, %1}, %2;" : "=f"(f.x), "=f"(f.y) : "l"(v)); return f;
}

// ---- activations ----
__device__ __forceinline__ float sigm(float x) {
    return __fdividef(1.0f, 1.0f + __expf(-x));
}
__device__ __forceinline__ float tanh_(float x) {
    float a = fabsf(x);
    float e = __expf(-2.0f * a);
    float t = __fdividef(1.0f - e, 1.0f + e);
    return copysignf(t, x);
}

// ---- prologue: repack weights gate-interleaved + bank-swizzled, chunk-major
//      pack[c][j][kk][g] = W[(g*128+j)][c*8 + (kk ^ (j&7))]  (identical to R12) ----
__global__ void repack_kernel(const float* __restrict__ eWhh0, const float* __restrict__ eWih1,
                              const float* __restrict__ eWhh1, const float* __restrict__ dWhh0,
                              const float* __restrict__ dWih1, const float* __restrict__ dWhh1,
                              const float* __restrict__ eWih0)
{
    int idx = blockIdx.x * 256 + threadIdx.x;
    if (idx < 6 * PACK_M) {
        int m   = idx >> 16;
        int rem = idx & (PACK_M - 1);
        int c  = rem >> 12;
        int j  = (rem >> 5) & 127;
        int kk = (rem >> 2) & 7;
        int g  = rem & 3;
        int k  = kk ^ (j & 7);
        const float* W = m == 0 ? eWhh0 : m == 1 ? eWih1 : m == 2 ? eWhh1
                       : m == 3 ? dWhh0 : m == 4 ? dWih1 : dWhh1;
        g_wpack[idx] = W[(g * 128 + j) * 128 + c * 8 + k];
    } else if (idx < PACK_TOT) {
        int rem = idx - 6 * PACK_M;
        int c  = rem >> 12;
        int j  = (rem >> 5) & 127;
        int kk = (rem >> 2) & 7;
        int g  = rem & 3;
        int k  = kk ^ (j & 7);
        g_wpack[rem + 6 * PACK_M] = eWih0[(g * 128 + j) * 16 + c * 8 + k];
    }
}

__device__ __forceinline__ void init_acc(u64 acc[4][7], const float b[4])
{
#pragma unroll
    for (int g = 0; g < 4; g++) {
        u64 bb = pk2(b[g]);
#pragma unroll
        for (int p = 0; p < 7; p++) acc[g][p] = bb;
    }
}

// ---- cp.async issue of one 16KB chunk (coalesced 16B units) ----
__device__ __forceinline__ void issue_chunk(const float* __restrict__ base, int c, int buf,
                                            uint32_t smem_u32, int tid)
{
    uint32_t dst = smem_u32 + (uint32_t)((OFF_WBUF + buf * CHUNKF) * 4 + tid * 16);
    const float* src = base + c * CHUNKF + tid * 4;
#pragma unroll
    for (int i = 0; i < 4; i++)
        asm volatile("cp.async.cg.shared.global [%0], [%1], 16;"
                     :: "r"(dst + (uint32_t)(i * 4096)), "l"(src + i * 1024));
    asm volatile("cp.async.commit_group;" ::: "memory");
}

// ---- streamed GEMM over K = NCH*8, continuous pipeline:
//      chunk 0 was issued by the PREDECESSOR gemm; at our last chunk we issue
//      nextWp's chunk 0 (buf0). One barrier per chunk. ----
template<int NCH, int STRIDE>
__device__ __forceinline__ void gemm_cp(u64 acc[4][7],
                                        const float* __restrict__ Wp,
                                        const float* __restrict__ nextWp,
                                        const float* __restrict__ hb,
                                        const char* __restrict__ smc,
                                        uint32_t smem_u32, int tid, int j)
{
    const uint32_t jx16 = (uint32_t)((j & 7) << 4);
#pragma unroll 1
    for (int c = 0; c < NCH; c++) {
        asm volatile("cp.async.wait_group 0;" ::: "memory");
        __syncthreads();                 // chunk c visible; other buffer's readers done
        if (c + 1 < NCH)      issue_chunk(Wp, c + 1, (c + 1) & 1, smem_u32, tid);
        else if (nextWp)      issue_chunk(nextWp, 0, 0, smem_u32, tid);
        const uint32_t wbx = (uint32_t)((OFF_WBUF + (c & 1) * CHUNKF + j * 32) * 4) ^ jx16;
        const float* hc = hb + c * 8 * STRIDE;
#pragma unroll
        for (int k = 0; k < 8; k++) {
            float4 wv = *(const float4*)(smc + (wbx ^ (uint32_t)(k << 4)));
            u64 b0 = pk2(wv.x);
            u64 b1 = pk2(wv.y);
            u64 b2 = pk2(wv.z);
            u64 b3 = pk2(wv.w);
            const float* hk = hc + k * STRIDE;
            ulonglong2 q0 = ((const ulonglong2*)hk)[0];
            ulonglong2 q1 = ((const ulonglong2*)hk)[1];
            ulonglong2 q2 = ((const ulonglong2*)hk)[2];
            u64 a6 = ((const u64*)hk)[6];
            u64 a[7] = {q0.x, q0.y, q1.x, q1.y, q2.x, q2.y, a6};
#pragma unroll
            for (int p = 0; p < 7; p++) {
                acc[0][p] = f2fma(a[p], b0, acc[0][p]);
                acc[1][p] = f2fma(a[p], b1, acc[1][p]);
                acc[2][p] = f2fma(a[p], b2, acc[2][p]);
                acc[3][p] = f2fma(a[p], b3, acc[3][p]);
            }
        }
    }
    __syncthreads();   // protect buf1 + h/x rewrites after this gemm
}

// ---- LSTM pointwise epilogue: unit j, 14 rows at half rb; c in smem ----
__device__ __forceinline__ void epilogue(u64 acc[4][7],
                                         float* __restrict__ cs,
                                         float* __restrict__ hs,
                                         int j, int rb)
{
    float2* cp = (float2*)(cs + j * CPAD + rb * 16);
    float2* hp = (float2*)(hs + j * HPAD + rb * 16);
#pragma unroll
    for (int p = 0; p < 7; p++) {
        float2 gi = up2(acc[0][p]);
        float2 gf = up2(acc[1][p]);
        float2 gg = up2(acc[2][p]);
        float2 go = up2(acc[3][p]);
        float2 c = cp[p];
        float cn0 = sigm(gf.x) * c.x + sigm(gi.x) * tanh_(gg.x);
        float cn1 = sigm(gf.y) * c.y + sigm(gi.y) * tanh_(gg.y);
        cp[p] = make_float2(cn0, cn1);
        hp[p] = make_float2(sigm(go.x) * tanh_(cn0), sigm(go.y) * tanh_(cn1));
    }
}

__global__ void __launch_bounds__(NT, 2)
lstm_traj_kernel(const float* __restrict__ x,
                 const float* __restrict__ ebih0, const float* __restrict__ ebhh0,
                 const float* __restrict__ ebih1, const float* __restrict__ ebhh1,
                 const float* __restrict__ dWih0,
                 const float* __restrict__ dbih0, const float* __restrict__ dbhh0,
                 const float* __restrict__ dbih1, const float* __restrict__ dbhh1,
                 const float* __restrict__ fcW,  const float* __restrict__ fcb,
                 float* __restrict__ out)
{
    extern __shared__ float sm[];
    const char* smc = (const char*)sm;
    uint32_t smem_u32 = (uint32_t)__cvta_generic_to_shared(sm);
    const int tid = threadIdx.x;
    const int j  = tid >> 1;            // hidden unit 0..127
    const int rb = tid & 1;             // row half: slots rb*16 .. rb*16+13
    const int bid = blockIdx.x;
    const int nrows = (bid < NBIG) ? 28 : 27;
    const int gr0 = (bid < NBIG) ? bid * 28 : NBIG * 28 + (bid - NBIG) * 27;

    // biases, combined, in registers
    float be0[4], be1[4], bd0[4], bd1[4];
#pragma unroll
    for (int g = 0; g < 4; g++) {
        int idx = g * 128 + j;
        be0[g] = ebih0[idx] + ebhh0[idx];
        be1[g] = ebih1[idx] + ebhh1[idx];
        bd0[g] = dbih0[idx] + dbhh0[idx];
        bd1[g] = dbih1[idx] + dbhh1[idx];
    }

    // zero h & c states; stage FC weights + dWih0 (once)
    for (int i = tid; i < OFF_WBUF; i += NT) sm[i] = 0.0f;
    sm[OFF_FC + tid] = fcW[tid];
    if (tid < 2) sm[OFF_FCB + tid] = fcb[tid];
    for (int i = tid; i < 1024; i += NT) sm[OFF_DW + i] = dWih0[i];
    __syncthreads();

    const float* hb0 = sm + OFF_H0 + rb * 16;
    const float* hb1 = sm + OFF_H1 + rb * 16;
    const float* xb  = sm + OFF_XS + rb * 16;

    // packed weight bases
    const float* pWhh0  = g_wpack + 0 * PACK_M;
    const float* pWih1  = g_wpack + 1 * PACK_M;
    const float* pWhh1  = g_wpack + 2 * PACK_M;
    const float* pdWhh0 = g_wpack + 3 * PACK_M;
    const float* pdWih1 = g_wpack + 4 * PACK_M;
    const float* pdWhh1 = g_wpack + 5 * PACK_M;
    const float* pWih0  = g_wpack + 6 * PACK_M;

    // prime the pipeline: issue ih0 chunk 0 into buf0
    issue_chunk(pWih0, 0, 0, smem_u32, tid);

    // ======================= ENCODER =======================
#pragma unroll 1
    for (int t = 0; t < TT; t++) {
        // stage x_t transposed: xs[k][slot]; visibility via ih0's first barrier
        for (int e = tid; e < 16 * BRMX; e += NT) {
            int r = e >> 4, k = e & 15;
            int slot = r + ((r >= RH) ? 2 : 0);
            int rr = (r < nrows) ? r : (nrows - 1);
            sm[OFF_XS + k * XPAD + slot] = x[(size_t)(gr0 + rr) * (TT * 16) + t * 16 + k];
        }

        u64 acc[4][7];
        // layer 0
        init_acc(acc, be0);
        gemm_cp<2, XPAD>(acc, pWih0, pWhh0, xb, smc, smem_u32, tid, j);
        gemm_cp<16, HPAD>(acc, pWhh0, pWih1, hb0, smc, smem_u32, tid, j);
        epilogue(acc, sm + OFF_C0, sm + OFF_H0, j, rb);
        // layer 1 (its first barrier orders epilogue0's h writes)
        init_acc(acc, be1);
        gemm_cp<16, HPAD>(acc, pWih1, pWhh1, hb0, smc, smem_u32, tid, j);
        gemm_cp<16, HPAD>(acc, pWhh1, (t < TT - 1) ? pWih0 : pdWhh0, hb1, smc, smem_u32, tid, j);
        epilogue(acc, sm + OFF_C1, sm + OFF_H1, j, rb);
        __syncthreads();   // h1 writes visible before next step
    }

    // ======================= DECODER setup =======================
    if (tid < BRMX) {   // dec_in = x[:, 99, :2]
        int r = tid;
        int slot = r + ((r >= RH) ? 2 : 0);
        int rr = (r < nrows) ? r : (nrows - 1);
        size_t base = (size_t)(gr0 + rr) * (TT * 16) + 99 * 16;
        sm[OFF_XS + slot]        = x[base + 0];
        sm[OFF_XS + XPAD + slot] = x[base + 1];
    }
    __syncthreads();

    // ======================= DECODER =======================
#pragma unroll 1
    for (int t = 0; t < TGTN; t++) {
        u64 acc[4][7];
        // layer 0: K=2 input from resident dW [512][2] + K=128 recurrent
        init_acc(acc, bd0);
#pragma unroll
        for (int k = 0; k < 2; k++) {
            const float* dw = sm + OFF_DW;
            u64 b0 = pk2(dw[(j      ) * 2 + k]);
            u64 b1 = pk2(dw[(j + 128) * 2 + k]);
            u64 b2 = pk2(dw[(j + 256) * 2 + k]);
            u64 b3 = pk2(dw[(j + 384) * 2 + k]);
            const float* hk = xb + k * XPAD;
            ulonglong2 q0 = ((const ulonglong2*)hk)[0];
            ulonglong2 q1 = ((const ulonglong2*)hk)[1];
            ulonglong2 q2 = ((const ulonglong2*)hk)[2];
            u64 a6 = ((const u64*)hk)[6];
            u64 a[7] = {q0.x, q0.y, q1.x, q1.y, q2.x, q2.y, a6};
#pragma unroll
            for (int p = 0; p < 7; p++) {
                acc[0][p] = f2fma(a[p], b0, acc[0][p]);
                acc[1][p] = f2fma(a[p], b1, acc[1][p]);
                acc[2][p] = f2fma(a[p], b2, acc[2][p]);
                acc[3][p] = f2fma(a[p], b3, acc[3][p]);
            }
        }
        gemm_cp<16, HPAD>(acc, pdWhh0, pdWih1, hb0, smc, smem_u32, tid, j);
        epilogue(acc, sm + OFF_C0, sm + OFF_H0, j, rb);
        // layer 1
        init_acc(acc, bd1);
        gemm_cp<16, HPAD>(acc, pdWih1, pdWhh1, hb0, smc, smem_u32, tid, j);
        gemm_cp<16, HPAD>(acc, pdWhh1, (t < TGTN - 1) ? pdWhh0 : (const float*)nullptr,
                          hb1, smc, smem_u32, tid, j);
        epilogue(acc, sm + OFF_C1, sm + OFF_H1, j, rb);
        __syncthreads();   // h1 ready for FC

        // FC + output + feedback
        if (tid < 2 * BRMX) {
            int r = tid >> 1;
            int o = tid & 1;
            int slot = r + ((r >= RH) ? 2 : 0);
            float s = sm[OFF_FCB + o];
            const float* fw = sm + OFF_FC + o * 128;
            const float* hv = sm + OFF_H1 + slot;
#pragma unroll 8
            for (int jj = 0; jj < 128; jj++) s += hv[jj * HPAD] * fw[jj];
            if (r < nrows) out[((size_t)(gr0 + r) * TGTN + t) * 2 + o] = s;
            sm[OFF_XS + o * XPAD + slot] = s;
        }
        __syncthreads();   // feedback visible before next step's K=2 accum
    }
}

extern "C" void kernel_launch(void* const* d_in, const int* in_sizes, int n_in,
                              void* d_out, int out_size)
{
    const float* x     = (const float*)d_in[0];
    const float* eWih0 = (const float*)d_in[2];
    const float* eWhh0 = (const float*)d_in[3];
    const float* ebih0 = (const float*)d_in[4];
    const float* ebhh0 = (const float*)d_in[5];
    const float* eWih1 = (const float*)d_in[6];
    const float* eWhh1 = (const float*)d_in[7];
    const float* ebih1 = (const float*)d_in[8];
    const float* ebhh1 = (const float*)d_in[9];
    const float* dWih0 = (const float*)d_in[10];
    const float* dWhh0 = (const float*)d_in[11];
    const float* dbih0 = (const float*)d_in[12];
    const float* dbhh0 = (const float*)d_in[13];
    const float* dWih1 = (const float*)d_in[14];
    const float* dWhh1 = (const float*)d_in[15];
    const float* dbih1 = (const float*)d_in[16];
    const float* dbhh1 = (const float*)d_in[17];
    const float* fcW   = (const float*)d_in[18];
    const float* fcb   = (const float*)d_in[19];
    float* out = (float*)d_out;

    // 1) repack weights gate-interleaved + bank-swizzled, chunk-major
    repack_kernel<<<(PACK_TOT + 255) / 256, 256>>>(
        eWhh0, eWih1, eWhh1, dWhh0, dWih1, dWhh1, eWih0);

    // 2) main kernel, balanced grid (2 CTAs per SM)
    cudaFuncSetAttribute(lstm_traj_kernel,
                         cudaFuncAttributeMaxDynamicSharedMemorySize, SMEM_BYTES);
    lstm_traj_kernel<<<GRID, NT, SMEM_BYTES>>>(
        x, ebih0, ebhh0, ebih1, ebhh1,
        dWih0, dbih0, dbhh0, dbih1, dbhh1,
        fcW, fcb, out);
}

// round 14
// speedup vs baseline: 3.3171x; 1.0590x over previous
#include <cuda_runtime.h>
#include <cstdint>

// Problem constants
#define BB    8192
#define TT    100
#define TGTN  60

#define NT    256     // threads per CTA (8 warps)
#define GRID  296     // 2 x 148 SMs -> perfectly balanced 2 CTAs/SM
#define NBIG  200     // first 200 CTAs take 28 rows, rest 27 (200*28+96*27=8192)
#define BRMX  28      // max rows per CTA
#define RH    14      // rows per half (rb)
#define HPAD  36      // h row stride (floats)
#define CPAD  32      // c row stride (floats)
#define XPAD  32      // x/feedback row stride (floats)
#define CHUNKF 4096   // one weight buffer: [128 j][8 kk][4 g] floats (16KB)

// Shared layout (float offsets, all 16B-aligned)
#define OFF_H0   0                 // [128][36] (slots 0..13,16..29 used)
#define OFF_H1   4608
#define OFF_C0   9216              // [128][32]
#define OFF_C1   13312
#define OFF_WBUF 17408             // 2 x CHUNKF (per-warp 2KB slices)
#define OFF_XS   25600             // [16][32]
#define OFF_FC   26112             // fcW [2][128]
#define OFF_FCB  26368             // fcb [2] + pad
#define OFF_DW   26372             // dWih0 native [512][2]
#define SMEM_FLOATS 27396
#define SMEM_BYTES  (SMEM_FLOATS*4)   // 109,584 B -> 2 CTAs/SM

// Packed-weight scratch: 6 big matrices [16 chunks][128][8][4] + eWih0 [2 chunks][128][8][4]
#define PACK_M   65536
#define PACK_TOT (6*PACK_M + 2*4096)
__device__ float g_wpack[PACK_TOT];

typedef unsigned long long u64;

// ---- packed f32x2 helpers ----
__device__ __forceinline__ u64 pk2(float x) {
    u64 r; asm("mov.b64 %0, {%1, %1};" : "=l"(r) : "f"(x)); return r;
}
__device__ __forceinline__ u64 f2fma(u64 a, u64 b, u64 c) {
    u64 d; asm("fma.rn.f32x2 %0, %1, %2, %3;" : "=l"(d) : "l"(a), "l"(b), "l"(c)); return d;
}
__device__ __forceinline__ float2 up2(u64 v) {
    float2 f; asm("mov.b64 {%0, %1}, %2;" : "=f"(f.x), "=f"(f.y) : "l"(v)); return f;
}

// ---- activations ----
__device__ __forceinline__ float sigm(float x) {
    return __fdividef(1.0f, 1.0f + __expf(-x));
}
__device__ __forceinline__ float tanh_(float x) {
    float a = fabsf(x);
    float e = __expf(-2.0f * a);
    float t = __fdividef(1.0f - e, 1.0f + e);
    return copysignf(t, x);
}

// ---- prologue: repack weights gate-interleaved + bank-swizzled, chunk-major
//      pack[c][j][kk][g] = W[(g*128+j)][c*8 + (kk ^ (j&7))]  (identical to R13) ----
__global__ void repack_kernel(const float* __restrict__ eWhh0, const float* __restrict__ eWih1,
                              const float* __restrict__ eWhh1, const float* __restrict__ dWhh0,
                              const float* __restrict__ dWih1, const float* __restrict__ dWhh1,
                              const float* __restrict__ eWih0)
{
    int idx = blockIdx.x * 256 + threadIdx.x;
    if (idx < 6 * PACK_M) {
        int m   = idx >> 16;
        int rem = idx & (PACK_M - 1);
        int c  = rem >> 12;
        int j  = (rem >> 5) & 127;
        int kk = (rem >> 2) & 7;
        int g  = rem & 3;
        int k  = kk ^ (j & 7);
        const float* W = m == 0 ? eWhh0 : m == 1 ? eWih1 : m == 2 ? eWhh1
                       : m == 3 ? dWhh0 : m == 4 ? dWih1 : dWhh1;
        g_wpack[idx] = W[(g * 128 + j) * 128 + c * 8 + k];
    } else if (idx < PACK_TOT) {
        int rem = idx - 6 * PACK_M;
        int c  = rem >> 12;
        int j  = (rem >> 5) & 127;
        int kk = (rem >> 2) & 7;
        int g  = rem & 3;
        int k  = kk ^ (j & 7);
        g_wpack[rem + 6 * PACK_M] = eWih0[(g * 128 + j) * 16 + c * 8 + k];
    }
}

__device__ __forceinline__ void init_acc(u64 acc[4][7], const float b[4])
{
#pragma unroll
    for (int g = 0; g < 4; g++) {
        u64 bb = pk2(b[g]);
#pragma unroll
        for (int p = 0; p < 7; p++) acc[g][p] = bb;
    }
}

// ---- per-WARP cp.async of this warp's 2KB slice of one chunk.
//      Warp W owns bytes [W*2048, W*2048+2048) of the chunk (j in [16W,16W+16)),
//      which is exactly the region it later reads -> no cross-warp sync needed. ----
__device__ __forceinline__ void issue_slice(const float* __restrict__ base, int c, int buf,
                                            uint32_t smem_u32, uint32_t boff)
{
    uint32_t dst = smem_u32 + (uint32_t)((OFF_WBUF + buf * CHUNKF) * 4) + boff;
    const char* src = (const char*)(base + c * CHUNKF) + boff;
#pragma unroll
    for (int i = 0; i < 4; i++)
        asm volatile("cp.async.cg.shared.global [%0], [%1], 16;"
                     :: "r"(dst + (uint32_t)(i * 512)), "l"(src + i * 512));
    asm volatile("cp.async.commit_group;" ::: "memory");
}

// ---- streamed GEMM over K = NCH*8, per-warp self-synchronized pipeline:
//      chunk 0 was issued by the PREDECESSOR gemm (this warp); at the last
//      chunk we issue nextWp's chunk 0 (buf0). NO __syncthreads inside. ----
template<int NCH, int STRIDE>
__device__ __forceinline__ void gemm_cp(u64 acc[4][7],
                                        const float* __restrict__ Wp,
                                        const float* __restrict__ nextWp,
                                        const float* __restrict__ hb,
                                        const char* __restrict__ smc,
                                        uint32_t smem_u32, uint32_t boff, int j)
{
    const uint32_t jx16 = (uint32_t)((j & 7) << 4);
#pragma unroll 1
    for (int c = 0; c < NCH; c++) {
        asm volatile("cp.async.wait_group 0;" ::: "memory");
        __syncwarp();                    // own slice visible warp-wide; own buf free
        if (c + 1 < NCH)      issue_slice(Wp, c + 1, (c + 1) & 1, smem_u32, boff);
        else if (nextWp)      issue_slice(nextWp, 0, 0, smem_u32, boff);
        const uint32_t wbx = (uint32_t)((OFF_WBUF + (c & 1) * CHUNKF + j * 32) * 4) ^ jx16;
        const float* hc = hb + c * 8 * STRIDE;
#pragma unroll
        for (int k = 0; k < 8; k++) {
            float4 wv = *(const float4*)(smc + (wbx ^ (uint32_t)(k << 4)));
            u64 b0 = pk2(wv.x);
            u64 b1 = pk2(wv.y);
            u64 b2 = pk2(wv.z);
            u64 b3 = pk2(wv.w);
            const float* hk = hc + k * STRIDE;
            ulonglong2 q0 = ((const ulonglong2*)hk)[0];
            ulonglong2 q1 = ((const ulonglong2*)hk)[1];
            ulonglong2 q2 = ((const ulonglong2*)hk)[2];
            u64 a6 = ((const u64*)hk)[6];
            u64 a[7] = {q0.x, q0.y, q1.x, q1.y, q2.x, q2.y, a6};
#pragma unroll
            for (int p = 0; p < 7; p++) {
                acc[0][p] = f2fma(a[p], b0, acc[0][p]);
                acc[1][p] = f2fma(a[p], b1, acc[1][p]);
                acc[2][p] = f2fma(a[p], b2, acc[2][p]);
                acc[3][p] = f2fma(a[p], b3, acc[3][p]);
            }
        }
    }
}

// ---- LSTM pointwise epilogue: unit j, 14 rows at half rb; c in smem ----
__device__ __forceinline__ void epilogue(u64 acc[4][7],
                                         float* __restrict__ cs,
                                         float* __restrict__ hs,
                                         int j, int rb)
{
    float2* cp = (float2*)(cs + j * CPAD + rb * 16);
    float2* hp = (float2*)(hs + j * HPAD + rb * 16);
#pragma unroll
    for (int p = 0; p < 7; p++) {
        float2 gi = up2(acc[0][p]);
        float2 gf = up2(acc[1][p]);
        float2 gg = up2(acc[2][p]);
        float2 go = up2(acc[3][p]);
        float2 c = cp[p];
        float cn0 = sigm(gf.x) * c.x + sigm(gi.x) * tanh_(gg.x);
        float cn1 = sigm(gf.y) * c.y + sigm(gi.y) * tanh_(gg.y);
        cp[p] = make_float2(cn0, cn1);
        hp[p] = make_float2(sigm(go.x) * tanh_(cn0), sigm(go.y) * tanh_(cn1));
    }
}

__global__ void __launch_bounds__(NT, 2)
lstm_traj_kernel(const float* __restrict__ x,
                 const float* __restrict__ ebih0, const float* __restrict__ ebhh0,
                 const float* __restrict__ ebih1, const float* __restrict__ ebhh1,
                 const float* __restrict__ dWih0,
                 const float* __restrict__ dbih0, const float* __restrict__ dbhh0,
                 const float* __restrict__ dbih1, const float* __restrict__ dbhh1,
                 const float* __restrict__ fcW,  const float* __restrict__ fcb,
                 float* __restrict__ out)
{
    extern __shared__ float sm[];
    const char* smc = (const char*)sm;
    uint32_t smem_u32 = (uint32_t)__cvta_generic_to_shared(sm);
    const int tid = threadIdx.x;
    const int j  = tid >> 1;            // hidden unit 0..127
    const int rb = tid & 1;             // row half: slots rb*16 .. rb*16+13
    const uint32_t boff = (uint32_t)(((tid >> 5) << 11) | ((tid & 31) << 4));  // warp-slice byte offset
    const int bid = blockIdx.x;
    const int nrows = (bid < NBIG) ? 28 : 27;
    const int gr0 = (bid < NBIG) ? bid * 28 : NBIG * 28 + (bid - NBIG) * 27;

    // biases, combined, in registers
    float be0[4], be1[4], bd0[4], bd1[4];
#pragma unroll
    for (int g = 0; g < 4; g++) {
        int idx = g * 128 + j;
        be0[g] = ebih0[idx] + ebhh0[idx];
        be1[g] = ebih1[idx] + ebhh1[idx];
        bd0[g] = dbih0[idx] + dbhh0[idx];
        bd1[g] = dbih1[idx] + dbhh1[idx];
    }

    // zero h & c states; stage FC weights + dWih0 (once)
    for (int i = tid; i < OFF_WBUF; i += NT) sm[i] = 0.0f;
    sm[OFF_FC + tid] = fcW[tid];
    if (tid < 2) sm[OFF_FCB + tid] = fcb[tid];
    for (int i = tid; i < 1024; i += NT) sm[OFF_DW + i] = dWih0[i];

    // stage xs for t=0
    for (int e = tid; e < 16 * BRMX; e += NT) {
        int r = e >> 4, k = e & 15;
        int slot = r + ((r >= RH) ? 2 : 0);
        int rr = (r < nrows) ? r : (nrows - 1);
        sm[OFF_XS + k * XPAD + slot] = x[(size_t)(gr0 + rr) * (TT * 16) + k];
    }
    __syncthreads();

    const float* hb0 = sm + OFF_H0 + rb * 16;
    const float* hb1 = sm + OFF_H1 + rb * 16;
    const float* xb  = sm + OFF_XS + rb * 16;

    // packed weight bases
    const float* pWhh0  = g_wpack + 0 * PACK_M;
    const float* pWih1  = g_wpack + 1 * PACK_M;
    const float* pWhh1  = g_wpack + 2 * PACK_M;
    const float* pdWhh0 = g_wpack + 3 * PACK_M;
    const float* pdWih1 = g_wpack + 4 * PACK_M;
    const float* pdWhh1 = g_wpack + 5 * PACK_M;
    const float* pWih0  = g_wpack + 6 * PACK_M;

    // prime the per-warp pipeline: ih0 chunk 0 into buf0
    issue_slice(pWih0, 0, 0, smem_u32, boff);

    // ======================= ENCODER =======================
#pragma unroll 1
    for (int t = 0; t < TT; t++) {
        u64 acc[4][7];
        // layer 0 (reads xs, h0; no cross-warp sync inside)
        init_acc(acc, be0);
        gemm_cp<2, XPAD>(acc, pWih0, pWhh0, xb, smc, smem_u32, boff, j);
        gemm_cp<16, HPAD>(acc, pWhh0, pWih1, hb0, smc, smem_u32, boff, j);
        __syncthreads();                 // all warps done reading h0/xs
        epilogue(acc, sm + OFF_C0, sm + OFF_H0, j, rb);
        __syncthreads();                 // new h0 visible
        // layer 1
        init_acc(acc, be1);
        gemm_cp<16, HPAD>(acc, pWih1, pWhh1, hb0, smc, smem_u32, boff, j);
        gemm_cp<16, HPAD>(acc, pWhh1, (t < TT - 1) ? pWih0 : pdWhh0, hb1, smc, smem_u32, boff, j);
        __syncthreads();                 // all warps done reading h1
        epilogue(acc, sm + OFF_C1, sm + OFF_H1, j, rb);
        // stage xs for t+1 (readers of xs[t] finished at pre-epi0 barrier)
        if (t < TT - 1) {
            for (int e = tid; e < 16 * BRMX; e += NT) {
                int r = e >> 4, k = e & 15;
                int slot = r + ((r >= RH) ? 2 : 0);
                int rr = (r < nrows) ? r : (nrows - 1);
                sm[OFF_XS + k * XPAD + slot] = x[(size_t)(gr0 + rr) * (TT * 16) + (t + 1) * 16 + k];
            }
        }
        __syncthreads();                 // h1 + xs visible
    }

    // ======================= DECODER setup =======================
    if (tid < BRMX) {   // dec_in = x[:, 99, :2]
        int r = tid;
        int slot = r + ((r >= RH) ? 2 : 0);
        int rr = (r < nrows) ? r : (nrows - 1);
        size_t base = (size_t)(gr0 + rr) * (TT * 16) + 99 * 16;
        sm[OFF_XS + slot]        = x[base + 0];
        sm[OFF_XS + XPAD + slot] = x[base + 1];
    }
    __syncthreads();

    // ======================= DECODER =======================
#pragma unroll 1
    for (int t = 0; t < TGTN; t++) {
        u64 acc[4][7];
        // layer 0: K=2 input from resident dW [512][2] + K=128 recurrent
        init_acc(acc, bd0);
#pragma unroll
        for (int k = 0; k < 2; k++) {
            const float* dw = sm + OFF_DW;
            u64 b0 = pk2(dw[(j      ) * 2 + k]);
            u64 b1 = pk2(dw[(j + 128) * 2 + k]);
            u64 b2 = pk2(dw[(j + 256) * 2 + k]);
            u64 b3 = pk2(dw[(j + 384) * 2 + k]);
            const float* hk = xb + k * XPAD;
            ulonglong2 q0 = ((const ulonglong2*)hk)[0];
            ulonglong2 q1 = ((const ulonglong2*)hk)[1];
            ulonglong2 q2 = ((const ulonglong2*)hk)[2];
            u64 a6 = ((const u64*)hk)[6];
            u64 a[7] = {q0.x, q0.y, q1.x, q1.y, q2.x, q2.y, a6};
#pragma unroll
            for (int p = 0; p < 7; p++) {
                acc[0][p] = f2fma(a[p], b0, acc[0][p]);
                acc[1][p] = f2fma(a[p], b1, acc[1][p]);
                acc[2][p] = f2fma(a[p], b2, acc[2][p]);
                acc[3][p] = f2fma(a[p], b3, acc[3][p]);
            }
        }
        gemm_cp<16, HPAD>(acc, pdWhh0, pdWih1, hb0, smc, smem_u32, boff, j);
        __syncthreads();                 // done reading h0/xs
        epilogue(acc, sm + OFF_C0, sm + OFF_H0, j, rb);
        __syncthreads();                 // new h0 visible
        // layer 1
        init_acc(acc, bd1);
        gemm_cp<16, HPAD>(acc, pdWih1, pdWhh1, hb0, smc, smem_u32, boff, j);
        gemm_cp<16, HPAD>(acc, pdWhh1, (t < TGTN - 1) ? pdWhh0 : (const float*)nullptr,
                          hb1, smc, smem_u32, boff, j);
        __syncthreads();                 // done reading h1
        epilogue(acc, sm + OFF_C1, sm + OFF_H1, j, rb);
        __syncthreads();                 // h1 ready for FC

        // FC + output + feedback
        if (tid < 2 * BRMX) {
            int r = tid >> 1;
            int o = tid & 1;
            int slot = r + ((r >= RH) ? 2 : 0);
            float s = sm[OFF_FCB + o];
            const float* fw = sm + OFF_FC + o * 128;
            const float* hv = sm + OFF_H1 + slot;
#pragma unroll 8
            for (int jj = 0; jj < 128; jj++) s += hv[jj * HPAD] * fw[jj];
            if (r < nrows) out[((size_t)(gr0 + r) * TGTN + t) * 2 + o] = s;
            sm[OFF_XS + o * XPAD + slot] = s;
        }
        __syncthreads();                 // feedback visible before next step's K=2
    }
}

extern "C" void kernel_launch(void* const* d_in, const int* in_sizes, int n_in,
                              void* d_out, int out_size)
{
    const float* x     = (const float*)d_in[0];
    const float* eWih0 = (const float*)d_in[2];
    const float* eWhh0 = (const float*)d_in[3];
    const float* ebih0 = (const float*)d_in[4];
    const float* ebhh0 = (const float*)d_in[5];
    const float* eWih1 = (const float*)d_in[6];
    const float* eWhh1 = (const float*)d_in[7];
    const float* ebih1 = (const float*)d_in[8];
    const float* ebhh1 = (const float*)d_in[9];
    const float* dWih0 = (const float*)d_in[10];
    const float* dWhh0 = (const float*)d_in[11];
    const float* dbih0 = (const float*)d_in[12];
    const float* dbhh0 = (const float*)d_in[13];
    const float* dWih1 = (const float*)d_in[14];
    const float* dWhh1 = (const float*)d_in[15];
    const float* dbih1 = (const float*)d_in[16];
    const float* dbhh1 = (const float*)d_in[17];
    const float* fcW   = (const float*)d_in[18];
    const float* fcb   = (const float*)d_in[19];
    float* out = (float*)d_out;

    // 1) repack weights gate-interleaved + bank-swizzled, chunk-major
    repack_kernel<<<(PACK_TOT + 255) / 256, 256>>>(
        eWhh0, eWih1, eWhh1, dWhh0, dWih1, dWhh1, eWih0);

    // 2) main kernel, balanced grid (2 CTAs per SM)
    cudaFuncSetAttribute(lstm_traj_kernel,
                         cudaFuncAttributeMaxDynamicSharedMemorySize, SMEM_BYTES);
    lstm_traj_kernel<<<GRID, NT, SMEM_BYTES>>>(
        x, ebih0, ebhh0, ebih1, ebhh1,
        dWih0, dbih0, dbhh0, dbih1, dbhh1,
        fcW, fcb, out);
}

// round 15
// speedup vs baseline: 3.3175x; 1.0001x over previous
#include <cuda_runtime.h>
#include <cstdint>

// Problem constants
#define BB    8192
#define TT    100
#define TGTN  60

#define NT    256     // threads per CTA (8 warps)
#define GRID  296     // 2 x 148 SMs -> perfectly balanced 2 CTAs/SM
#define NBIG  200     // first 200 CTAs take 28 rows, rest 27 (200*28+96*27=8192)
#define BRMX  28      // max rows per CTA
#define RH    14      // rows per half (rb)
#define HPAD  36      // h row stride (floats)
#define CPAD  32      // c row stride (floats)
#define XPAD  32      // x/feedback row stride (floats)
#define CHUNKF 4096   // one weight buffer: [128 j][8 kk][4 g] floats (16KB)

// Shared layout (float offsets, all 16B-aligned)
#define OFF_H0   0                 // [128][36] (slots 0..13,16..29 used)
#define OFF_H1   4608
#define OFF_C0   9216              // [128][32]
#define OFF_C1   13312
#define OFF_WBUF 17408             // 2 x CHUNKF (per-warp 2KB slices)
#define OFF_XS   25600             // [16][32]
#define OFF_FC   26112             // fcW [2][128]
#define OFF_FCB  26368             // fcb [2] + pad
#define OFF_DW   26372             // dWih0 native [512][2]
#define SMEM_FLOATS 27396
#define SMEM_BYTES  (SMEM_FLOATS*4)   // 109,584 B -> 2 CTAs/SM

// Packed-weight scratch: 6 big matrices [16 chunks][128][8][4] + eWih0 [2 chunks][128][8][4]
#define PACK_M   65536
#define PACK_TOT (6*PACK_M + 2*4096)
__device__ float g_wpack[PACK_TOT];

typedef unsigned long long u64;

// ---- packed f32x2 helpers ----
__device__ __forceinline__ u64 pk2(float x) {
    u64 r; asm("mov.b64 %0, {%1, %1};" : "=l"(r) : "f"(x)); return r;
}
__device__ __forceinline__ u64 f2fma(u64 a, u64 b, u64 c) {
    u64 d; asm("fma.rn.f32x2 %0, %1, %2, %3;" : "=l"(d) : "l"(a), "l"(b), "l"(c)); return d;
}
__device__ __forceinline__ float2 up2(u64 v) {
    float2 f; asm("mov.b64 {%0, %1}, %2;" : "=f"(f.x), "=f"(f.y) : "l"(v)); return f;
}

// ---- activations ----
__device__ __forceinline__ float sigm(float x) {
    return __fdividef(1.0f, 1.0f + __expf(-x));
}
__device__ __forceinline__ float tanh_(float x) {
    float a = fabsf(x);
    float e = __expf(-2.0f * a);
    float t = __fdividef(1.0f - e, 1.0f + e);
    return copysignf(t, x);
}

// ---- prologue: repack weights gate-interleaved + bank-swizzled, chunk-major
//      pack[c][j][kk][g] = W[(g*128+j)][c*8 + (kk ^ (j&7))]  (identical to R13) ----
__global__ void repack_kernel(const float* __restrict__ eWhh0, const float* __restrict__ eWih1,
                              const float* __restrict__ eWhh1, const float* __restrict__ dWhh0,
                              const float* __restrict__ dWih1, const float* __restrict__ dWhh1,
                              const float* __restrict__ eWih0)
{
    int idx = blockIdx.x * 256 + threadIdx.x;
    if (idx < 6 * PACK_M) {
        int m   = idx >> 16;
        int rem = idx & (PACK_M - 1);
        int c  = rem >> 12;
        int j  = (rem >> 5) & 127;
        int kk = (rem >> 2) & 7;
        int g  = rem & 3;
        int k  = kk ^ (j & 7);
        const float* W = m == 0 ? eWhh0 : m == 1 ? eWih1 : m == 2 ? eWhh1
                       : m == 3 ? dWhh0 : m == 4 ? dWih1 : dWhh1;
        g_wpack[idx] = W[(g * 128 + j) * 128 + c * 8 + k];
    } else if (idx < PACK_TOT) {
        int rem = idx - 6 * PACK_M;
        int c  = rem >> 12;
        int j  = (rem >> 5) & 127;
        int kk = (rem >> 2) & 7;
        int g  = rem & 3;
        int k  = kk ^ (j & 7);
        g_wpack[rem + 6 * PACK_M] = eWih0[(g * 128 + j) * 16 + c * 8 + k];
    }
}

__device__ __forceinline__ void init_acc(u64 acc[4][7], const float b[4])
{
#pragma unroll
    for (int g = 0; g < 4; g++) {
        u64 bb = pk2(b[g]);
#pragma unroll
        for (int p = 0; p < 7; p++) acc[g][p] = bb;
    }
}

// ---- per-WARP cp.async of this warp's 2KB slice of one chunk.
//      Warp W owns bytes [W*2048, W*2048+2048) of the chunk (j in [16W,16W+16)),
//      which is exactly the region it later reads -> no cross-warp sync needed. ----
__device__ __forceinline__ void issue_slice(const float* __restrict__ base, int c, int buf,
                                            uint32_t smem_u32, uint32_t boff)
{
    uint32_t dst = smem_u32 + (uint32_t)((OFF_WBUF + buf * CHUNKF) * 4) + boff;
    const char* src = (const char*)(base + c * CHUNKF) + boff;
#pragma unroll
    for (int i = 0; i < 4; i++)
        asm volatile("cp.async.cg.shared.global [%0], [%1], 16;"
                     :: "r"(dst + (uint32_t)(i * 512)), "l"(src + i * 512));
    asm volatile("cp.async.commit_group;" ::: "memory");
}

// ---- streamed GEMM over K = NCH*8, per-warp self-synchronized pipeline:
//      chunk 0 was issued by the PREDECESSOR gemm (this warp); at the last
//      chunk we issue nextWp's chunk 0 (buf0). NO __syncthreads inside. ----
template<int NCH, int STRIDE>
__device__ __forceinline__ void gemm_cp(u64 acc[4][7],
                                        const float* __restrict__ Wp,
                                        const float* __restrict__ nextWp,
                                        const float* __restrict__ hb,
                                        const char* __restrict__ smc,
                                        uint32_t smem_u32, uint32_t boff, int j)
{
    const uint32_t jx16 = (uint32_t)((j & 7) << 4);
#pragma unroll 1
    for (int c = 0; c < NCH; c++) {
        asm volatile("cp.async.wait_group 0;" ::: "memory");
        __syncwarp();                    // own slice visible warp-wide; own buf free
        if (c + 1 < NCH)      issue_slice(Wp, c + 1, (c + 1) & 1, smem_u32, boff);
        else if (nextWp)      issue_slice(nextWp, 0, 0, smem_u32, boff);
        const uint32_t wbx = (uint32_t)((OFF_WBUF + (c & 1) * CHUNKF + j * 32) * 4) ^ jx16;
        const float* hc = hb + c * 8 * STRIDE;
#pragma unroll
        for (int k = 0; k < 8; k++) {
            float4 wv = *(const float4*)(smc + (wbx ^ (uint32_t)(k << 4)));
            u64 b0 = pk2(wv.x);
            u64 b1 = pk2(wv.y);
            u64 b2 = pk2(wv.z);
            u64 b3 = pk2(wv.w);
            const float* hk = hc + k * STRIDE;
            ulonglong2 q0 = ((const ulonglong2*)hk)[0];
            ulonglong2 q1 = ((const ulonglong2*)hk)[1];
            ulonglong2 q2 = ((const ulonglong2*)hk)[2];
            u64 a6 = ((const u64*)hk)[6];
            u64 a[7] = {q0.x, q0.y, q1.x, q1.y, q2.x, q2.y, a6};
#pragma unroll
            for (int p = 0; p < 7; p++) {
                acc[0][p] = f2fma(a[p], b0, acc[0][p]);
                acc[1][p] = f2fma(a[p], b1, acc[1][p]);
                acc[2][p] = f2fma(a[p], b2, acc[2][p]);
                acc[3][p] = f2fma(a[p], b3, acc[3][p]);
            }
        }
    }
}

// ---- LSTM pointwise epilogue: unit j, 14 rows at half rb; c in smem ----
__device__ __forceinline__ void epilogue(u64 acc[4][7],
                                         float* __restrict__ cs,
                                         float* __restrict__ hs,
                                         int j, int rb)
{
    float2* cp = (float2*)(cs + j * CPAD + rb * 16);
    float2* hp = (float2*)(hs + j * HPAD + rb * 16);
#pragma unroll
    for (int p = 0; p < 7; p++) {
        float2 gi = up2(acc[0][p]);
        float2 gf = up2(acc[1][p]);
        float2 gg = up2(acc[2][p]);
        float2 go = up2(acc[3][p]);
        float2 c = cp[p];
        float cn0 = sigm(gf.x) * c.x + sigm(gi.x) * tanh_(gg.x);
        float cn1 = sigm(gf.y) * c.y + sigm(gi.y) * tanh_(gg.y);
        cp[p] = make_float2(cn0, cn1);
        hp[p] = make_float2(sigm(go.x) * tanh_(cn0), sigm(go.y) * tanh_(cn1));
    }
}

__global__ void __launch_bounds__(NT, 2)
lstm_traj_kernel(const float* __restrict__ x,
                 const float* __restrict__ ebih0, const float* __restrict__ ebhh0,
                 const float* __restrict__ ebih1, const float* __restrict__ ebhh1,
                 const float* __restrict__ dWih0,
                 const float* __restrict__ dbih0, const float* __restrict__ dbhh0,
                 const float* __restrict__ dbih1, const float* __restrict__ dbhh1,
                 const float* __restrict__ fcW,  const float* __restrict__ fcb,
                 float* __restrict__ out)
{
    extern __shared__ float sm[];
    const char* smc = (const char*)sm;
    uint32_t smem_u32 = (uint32_t)__cvta_generic_to_shared(sm);
    const int tid = threadIdx.x;
    const int j  = tid >> 1;            // hidden unit 0..127
    const int rb = tid & 1;             // row half: slots rb*16 .. rb*16+13
    const uint32_t boff = (uint32_t)(((tid >> 5) << 11) | ((tid & 31) << 4));  // warp-slice byte offset
    const int bid = blockIdx.x;
    const int nrows = (bid < NBIG) ? 28 : 27;
    const int gr0 = (bid < NBIG) ? bid * 28 : NBIG * 28 + (bid - NBIG) * 27;

    // biases, combined, in registers
    float be0[4], be1[4], bd0[4], bd1[4];
#pragma unroll
    for (int g = 0; g < 4; g++) {
        int idx = g * 128 + j;
        be0[g] = ebih0[idx] + ebhh0[idx];
        be1[g] = ebih1[idx] + ebhh1[idx];
        bd0[g] = dbih0[idx] + dbhh0[idx];
        bd1[g] = dbih1[idx] + dbhh1[idx];
    }

    // zero h & c states; stage FC weights + dWih0 (once)
    for (int i = tid; i < OFF_WBUF; i += NT) sm[i] = 0.0f;
    sm[OFF_FC + tid] = fcW[tid];
    if (tid < 2) sm[OFF_FCB + tid] = fcb[tid];
    for (int i = tid; i < 1024; i += NT) sm[OFF_DW + i] = dWih0[i];

    // stage xs for t=0
    for (int e = tid; e < 16 * BRMX; e += NT) {
        int r = e >> 4, k = e & 15;
        int slot = r + ((r >= RH) ? 2 : 0);
        int rr = (r < nrows) ? r : (nrows - 1);
        sm[OFF_XS + k * XPAD + slot] = x[(size_t)(gr0 + rr) * (TT * 16) + k];
    }
    __syncthreads();

    const float* hb0 = sm + OFF_H0 + rb * 16;
    const float* hb1 = sm + OFF_H1 + rb * 16;
    const float* xb  = sm + OFF_XS + rb * 16;

    // packed weight bases
    const float* pWhh0  = g_wpack + 0 * PACK_M;
    const float* pWih1  = g_wpack + 1 * PACK_M;
    const float* pWhh1  = g_wpack + 2 * PACK_M;
    const float* pdWhh0 = g_wpack + 3 * PACK_M;
    const float* pdWih1 = g_wpack + 4 * PACK_M;
    const float* pdWhh1 = g_wpack + 5 * PACK_M;
    const float* pWih0  = g_wpack + 6 * PACK_M;

    // prime the per-warp pipeline: ih0 chunk 0 into buf0
    issue_slice(pWih0, 0, 0, smem_u32, boff);

    // ======================= ENCODER =======================
#pragma unroll 1
    for (int t = 0; t < TT; t++) {
        u64 acc[4][7];
        // layer 0 (reads xs, h0; no cross-warp sync inside)
        init_acc(acc, be0);
        gemm_cp<2, XPAD>(acc, pWih0, pWhh0, xb, smc, smem_u32, boff, j);
        gemm_cp<16, HPAD>(acc, pWhh0, pWih1, hb0, smc, smem_u32, boff, j);
        __syncthreads();                 // all warps done reading h0/xs
        epilogue(acc, sm + OFF_C0, sm + OFF_H0, j, rb);
        __syncthreads();                 // new h0 visible
        // layer 1
        init_acc(acc, be1);
        gemm_cp<16, HPAD>(acc, pWih1, pWhh1, hb0, smc, smem_u32, boff, j);
        gemm_cp<16, HPAD>(acc, pWhh1, (t < TT - 1) ? pWih0 : pdWhh0, hb1, smc, smem_u32, boff, j);
        __syncthreads();                 // all warps done reading h1
        epilogue(acc, sm + OFF_C1, sm + OFF_H1, j, rb);
        // stage xs for t+1 (readers of xs[t] finished at pre-epi0 barrier)
        if (t < TT - 1) {
            for (int e = tid; e < 16 * BRMX; e += NT) {
                int r = e >> 4, k = e & 15;
                int slot = r + ((r >= RH) ? 2 : 0);
                int rr = (r < nrows) ? r : (nrows - 1);
                sm[OFF_XS + k * XPAD + slot] = x[(size_t)(gr0 + rr) * (TT * 16) + (t + 1) * 16 + k];
            }
        }
        __syncthreads();                 // h1 + xs visible
    }

    // ======================= DECODER setup =======================
    if (tid < BRMX) {   // dec_in = x[:, 99, :2]
        int r = tid;
        int slot = r + ((r >= RH) ? 2 : 0);
        int rr = (r < nrows) ? r : (nrows - 1);
        size_t base = (size_t)(gr0 + rr) * (TT * 16) + 99 * 16;
        sm[OFF_XS + slot]        = x[base + 0];
        sm[OFF_XS + XPAD + slot] = x[base + 1];
    }
    __syncthreads();

    // ======================= DECODER =======================
#pragma unroll 1
    for (int t = 0; t < TGTN; t++) {
        u64 acc[4][7];
        // layer 0: K=2 input from resident dW [512][2] + K=128 recurrent
        init_acc(acc, bd0);
#pragma unroll
        for (int k = 0; k < 2; k++) {
            const float* dw = sm + OFF_DW;
            u64 b0 = pk2(dw[(j      ) * 2 + k]);
            u64 b1 = pk2(dw[(j + 128) * 2 + k]);
            u64 b2 = pk2(dw[(j + 256) * 2 + k]);
            u64 b3 = pk2(dw[(j + 384) * 2 + k]);
            const float* hk = xb + k * XPAD;
            ulonglong2 q0 = ((const ulonglong2*)hk)[0];
            ulonglong2 q1 = ((const ulonglong2*)hk)[1];
            ulonglong2 q2 = ((const ulonglong2*)hk)[2];
            u64 a6 = ((const u64*)hk)[6];
            u64 a[7] = {q0.x, q0.y, q1.x, q1.y, q2.x, q2.y, a6};
#pragma unroll
            for (int p = 0; p < 7; p++) {
                acc[0][p] = f2fma(a[p], b0, acc[0][p]);
                acc[1][p] = f2fma(a[p], b1, acc[1][p]);
                acc[2][p] = f2fma(a[p], b2, acc[2][p]);
                acc[3][p] = f2fma(a[p], b3, acc[3][p]);
            }
        }
        gemm_cp<16, HPAD>(acc, pdWhh0, pdWih1, hb0, smc, smem_u32, boff, j);
        __syncthreads();                 // done reading h0/xs
        epilogue(acc, sm + OFF_C0, sm + OFF_H0, j, rb);
        __syncthreads();                 // new h0 visible
        // layer 1
        init_acc(acc, bd1);
        gemm_cp<16, HPAD>(acc, pdWih1, pdWhh1, hb0, smc, smem_u32, boff, j);
        gemm_cp<16, HPAD>(acc, pdWhh1, (t < TGTN - 1) ? pdWhh0 : (const float*)nullptr,
                          hb1, smc, smem_u32, boff, j);
        __syncthreads();                 // done reading h1
        epilogue(acc, sm + OFF_C1, sm + OFF_H1, j, rb);
        __syncthreads();                 // h1 ready for FC

        // FC + output + feedback
        if (tid < 2 * BRMX) {
            int r = tid >> 1;
            int o = tid & 1;
            int slot = r + ((r >= RH) ? 2 : 0);
            float s = sm[OFF_FCB + o];
            const float* fw = sm + OFF_FC + o * 128;
            const float* hv = sm + OFF_H1 + slot;
#pragma unroll 8
            for (int jj = 0; jj < 128; jj++) s += hv[jj * HPAD] * fw[jj];
            if (r < nrows) out[((size_t)(gr0 + r) * TGTN + t) * 2 + o] = s;
            sm[OFF_XS + o * XPAD + slot] = s;
        }
        __syncthreads();                 // feedback visible before next step's K=2
    }
}

extern "C" void kernel_launch(void* const* d_in, const int* in_sizes, int n_in,
                              void* d_out, int out_size)
{
    const float* x     = (const float*)d_in[0];
    const float* eWih0 = (const float*)d_in[2];
    const float* eWhh0 = (const float*)d_in[3];
    const float* ebih0 = (const float*)d_in[4];
    const float* ebhh0 = (const float*)d_in[5];
    const float* eWih1 = (const float*)d_in[6];
    const float* eWhh1 = (const float*)d_in[7];
    const float* ebih1 = (const float*)d_in[8];
    const float* ebhh1 = (const float*)d_in[9];
    const float* dWih0 = (const float*)d_in[10];
    const float* dWhh0 = (const float*)d_in[11];
    const float* dbih0 = (const float*)d_in[12];
    const float* dbhh0 = (const float*)d_in[13];
    const float* dWih1 = (const float*)d_in[14];
    const float* dWhh1 = (const float*)d_in[15];
    const float* dbih1 = (const float*)d_in[16];
    const float* dbhh1 = (const float*)d_in[17];
    const float* fcW   = (const float*)d_in[18];
    const float* fcb   = (const float*)d_in[19];
    float* out = (float*)d_out;

    // 1) repack weights gate-interleaved + bank-swizzled, chunk-major
    repack_kernel<<<(PACK_TOT + 255) / 256, 256>>>(
        eWhh0, eWih1, eWhh1, dWhh0, dWih1, dWhh1, eWih0);

    // 2) main kernel, balanced grid (2 CTAs per SM)
    cudaFuncSetAttribute(lstm_traj_kernel,
                         cudaFuncAttributeMaxDynamicSharedMemorySize, SMEM_BYTES);
    lstm_traj_kernel<<<GRID, NT, SMEM_BYTES>>>(
        x, ebih0, ebhh0, ebih1, ebhh1,
        dWih0, dbih0, dbhh0, dbih1, dbhh1,
        fcW, fcb, out);
}